// round 1
// baseline (speedup 1.0000x reference)
#include <cuda_runtime.h>

#define GN 3
constexpr int NN = 16512;     // K + EXER entities
constexpr int KD = 128;       // embedding dim
constexpr int EE = 400000;    // edges per graph
constexpr int BB = 4096;      // batch
constexpr int TT = 204800;    // history length
constexpr int H1 = 512;
constexpr int H2 = 216;

// ---------------- scratch (static device globals; no allocation) ----------------
__device__ int   d_deg_s[GN][NN];
__device__ int   d_deg_d[GN][NN];
__device__ int   d_rowp[GN][NN + 1];
__device__ int   d_cur[GN][NN];
__device__ int   d_csrs[GN][EE];
__device__ float d_csrw[GN][EE];
__device__ float d_h0[NN * KD];
__device__ float d_h1[NN * KD];
__device__ float d_agg[GN][NN * KD];
__device__ float d_sumA[NN * KD];   // entity_emb + h1+h2+h3+h4  (full = /5)
__device__ float d_sumL[NN * KD];   // h3 + h4                    (disc_full = /2)
__device__ float d_stu[BB * KD];
__device__ int   d_segs[BB + 1];
__device__ float d_cvec[2 * KD];    // [0:128) concept@stuW[K:], [128:256) concept@exeW[K:]
__device__ float d_x[BB * KD];
__device__ float d_x1[BB * H1];
__device__ float d_x2[BB * H2];

__device__ __forceinline__ float sigm(float x) { return 1.f / (1.f + __expf(-x)); }

// ---------------- CSR build ----------------
__global__ void k_zero_deg() {
    int i = blockIdx.x * blockDim.x + threadIdx.x;
    if (i < GN * NN) { ((int*)d_deg_s)[i] = 0; ((int*)d_deg_d)[i] = 0; }
}

__global__ void k_degree(const int* __restrict__ s0, const int* __restrict__ d0,
                         const int* __restrict__ s1, const int* __restrict__ d1,
                         const int* __restrict__ s2, const int* __restrict__ d2) {
    int i = blockIdx.x * blockDim.x + threadIdx.x;
    if (i >= GN * EE) return;
    int g = i / EE, e = i - g * EE;
    const int* S = (g == 0) ? s0 : (g == 1) ? s1 : s2;
    const int* D = (g == 0) ? d0 : (g == 1) ? d1 : d2;
    atomicAdd(&d_deg_s[g][S[e]], 1);
    atomicAdd(&d_deg_d[g][D[e]], 1);
}

// exclusive scan of in-degree -> row_ptr (+cursor copy). one block per graph.
__global__ void k_scan() {
    __shared__ int sA[512], sB[512];
    int g = blockIdx.x, t = threadIdx.x;
    const int CH = (NN + 511) / 512;   // 33
    int base = t * CH;
    int s = 0;
    for (int i = 0; i < CH; i++) { int idx = base + i; if (idx < NN) s += d_deg_d[g][idx]; }
    sA[t] = s;
    __syncthreads();
    int* a = sA; int* b = sB;
    for (int off = 1; off < 512; off <<= 1) {
        b[t] = a[t] + ((t >= off) ? a[t - off] : 0);
        __syncthreads();
        int* tmp = a; a = b; b = tmp;
    }
    int incl = a[t];
    int total = a[511];
    int run = incl - s;
    for (int i = 0; i < CH; i++) {
        int idx = base + i;
        if (idx < NN) { d_rowp[g][idx] = run; d_cur[g][idx] = run; run += d_deg_d[g][idx]; }
    }
    if (t == 0) d_rowp[g][NN] = total;
}

__global__ void k_fill(const int* __restrict__ s0, const int* __restrict__ d0,
                       const int* __restrict__ s1, const int* __restrict__ d1,
                       const int* __restrict__ s2, const int* __restrict__ d2) {
    int i = blockIdx.x * blockDim.x + threadIdx.x;
    if (i >= GN * EE) return;
    int g = i / EE, e = i - g * EE;
    const int* S = (g == 0) ? s0 : (g == 1) ? s1 : s2;
    const int* D = (g == 0) ? d0 : (g == 1) ? d1 : d2;
    int sv = S[e], dv = D[e];
    int pos = atomicAdd(&d_cur[g][dv], 1);
    d_csrs[g][pos] = sv;
    float a = (float)max(d_deg_s[g][sv], 1);
    float b = (float)max(d_deg_d[g][dv], 1);
    d_csrw[g][pos] = rsqrtf(a * b);
}

__global__ void k_init(const float* __restrict__ ent) {
    int i = blockIdx.x * blockDim.x + threadIdx.x;
    if (i >= NN * KD) return;
    float v = ent[i];
    d_h0[i] = v;
    d_sumA[i] = v;
    d_sumL[i] = 0.f;
}

// ---------------- GCN layer: aggregation (warp per (g, dst-row)) ----------------
__global__ void __launch_bounds__(256) k_agg(int layer) {
    int gt = blockIdx.x * blockDim.x + threadIdx.x;
    int w = gt >> 5, lane = gt & 31;
    if (w >= GN * NN) return;
    int g = w / NN, n = w - g * NN;
    const float4* hin = (const float4*)((layer & 1) ? d_h1 : d_h0);
    int e0 = d_rowp[g][n], e1 = d_rowp[g][n + 1];
    float4 acc = make_float4(0.f, 0.f, 0.f, 0.f);
    for (int e = e0; e < e1; e++) {
        int s = d_csrs[g][e];
        float wt = d_csrw[g][e];
        float4 v = hin[s * 32 + lane];
        acc.x += wt * v.x; acc.y += wt * v.y; acc.z += wt * v.z; acc.w += wt * v.w;
    }
    ((float4*)d_agg[g])[n * 32 + lane] = acc;
}

// ---------------- GCN layer: combined GEMM h_new = sum_g agg_g @ W_gl + bias_sum
// 128x128 C tile, 256 threads, 8x8 register micro-tile, k-tiles of 8 over 3*128.
__global__ void __launch_bounds__(256) k_gemm(const float* __restrict__ Wg,
                                              const float* __restrict__ bg, int layer) {
    __shared__ float As[8][132];
    __shared__ float Bs[8][128];
    int row0 = blockIdx.x * 128;
    int tid = threadIdx.x;
    int tx = tid & 15, ty = tid >> 4;
    float c[8][8];
#pragma unroll
    for (int i = 0; i < 8; i++)
#pragma unroll
        for (int j = 0; j < 8; j++) c[i][j] = 0.f;

    for (int kt = 0; kt < 48; kt++) {
        int g = kt >> 4;
        int kk0 = (kt & 15) << 3;
        const float* Ag = d_agg[g];
#pragma unroll
        for (int i = tid; i < 1024; i += 256) {
            int r = i >> 3, kk = i & 7;
            int rr = row0 + r;
            As[kk][r] = (rr < NN) ? Ag[rr * KD + kk0 + kk] : 0.f;
        }
        const float* Wb = Wg + ((size_t)(g * 4 + layer) * KD + kk0) * KD;
#pragma unroll
        for (int i = tid; i < 1024; i += 256) {
            int kk = i >> 7, j = i & 127;
            Bs[kk][j] = Wb[kk * KD + j];
        }
        __syncthreads();
#pragma unroll
        for (int kk = 0; kk < 8; kk++) {
            float4 a0 = *(const float4*)&As[kk][ty * 8];
            float4 a1 = *(const float4*)&As[kk][ty * 8 + 4];
            float4 b0 = *(const float4*)&Bs[kk][tx * 8];
            float4 b1 = *(const float4*)&Bs[kk][tx * 8 + 4];
            float av[8] = {a0.x, a0.y, a0.z, a0.w, a1.x, a1.y, a1.z, a1.w};
            float bv[8] = {b0.x, b0.y, b0.z, b0.w, b1.x, b1.y, b1.z, b1.w};
#pragma unroll
            for (int i = 0; i < 8; i++)
#pragma unroll
                for (int j = 0; j < 8; j++) c[i][j] += av[i] * bv[j];
        }
        __syncthreads();
    }
    float bias[8];
#pragma unroll
    for (int j = 0; j < 8; j++) {
        int col = tx * 8 + j;
        bias[j] = bg[layer * KD + col] + bg[(4 + layer) * KD + col] + bg[(8 + layer) * KD + col];
    }
    float* hout = (layer & 1) ? d_h0 : d_h1;
    bool l2f = (layer >= 2);
#pragma unroll
    for (int i = 0; i < 8; i++) {
        int n = row0 + ty * 8 + i;
        if (n >= NN) continue;
        int base = n * KD + tx * 8;
#pragma unroll
        for (int q = 0; q < 2; q++) {
            float4 v;
            v.x = c[i][q * 4 + 0] + bias[q * 4 + 0];
            v.y = c[i][q * 4 + 1] + bias[q * 4 + 1];
            v.z = c[i][q * 4 + 2] + bias[q * 4 + 2];
            v.w = c[i][q * 4 + 3] + bias[q * 4 + 3];
            *(float4*)&hout[base + q * 4] = v;
            float4 sa = *(float4*)&d_sumA[base + q * 4];
            sa.x += v.x; sa.y += v.y; sa.z += v.z; sa.w += v.w;
            *(float4*)&d_sumA[base + q * 4] = sa;
            if (l2f) {
                float4 sl = *(float4*)&d_sumL[base + q * 4];
                sl.x += v.x; sl.y += v.y; sl.z += v.z; sl.w += v.w;
                *(float4*)&d_sumL[base + q * 4] = sl;
            }
        }
    }
}

// ---------------- head ----------------
__global__ void k_segstart(const int* __restrict__ seg) {
    int b = blockIdx.x * blockDim.x + threadIdx.x;
    if (b > BB) return;
    int lo = 0, hi = TT;
    while (lo < hi) { int m = (lo + hi) >> 1; if (seg[m] < b) lo = m + 1; else hi = m; }
    d_segs[b] = lo;
}

// stu[b] = mean over history of disc_full[K+hid]  (disc_full = sumL/2)
__global__ void k_stu(const int* __restrict__ hist) {
    int gt = blockIdx.x * blockDim.x + threadIdx.x;
    int w = gt >> 5, lane = gt & 31;
    if (w >= BB) return;
    int s = d_segs[w], e = d_segs[w + 1];
    const float4* SL = (const float4*)d_sumL;
    float4 acc = make_float4(0.f, 0.f, 0.f, 0.f);
    for (int t = s; t < e; t++) {
        int h = hist[t];
        float4 v = SL[(KD + h) * 32 + lane];
        acc.x += v.x; acc.y += v.y; acc.z += v.z; acc.w += v.w;
    }
    float inv = 0.5f / fmaxf((float)(e - s), 1.f);
    float4 o = make_float4(acc.x * inv, acc.y * inv, acc.z * inv, acc.w * inv);
    ((float4*)d_stu)[w * 32 + lane] = o;
}

// c_stu[j] = (full row j) . stuW[K:],  c_exer[j] = (full row j) . exeW[K:]   (full = sumA/5)
__global__ void k_cvec(const float* __restrict__ stuW, const float* __restrict__ exeW) {
    int tid = threadIdx.x;                  // 256 threads, 1 block
    int j = tid & 127;
    bool isE = tid >= 128;
    const float* wv = isE ? (exeW + KD) : (stuW + KD);
    float s = 0.f;
    for (int k = 0; k < KD; k++) s += d_sumA[j * KD + k] * wv[k];
    d_cvec[(isE ? KD : 0) + j] = s * 0.2f;
}

__global__ void k_x(const float* __restrict__ fsW, const float* __restrict__ fsB,
                    const float* __restrict__ feW, const float* __restrict__ feB,
                    const float* __restrict__ disc, const int* __restrict__ exid,
                    const float* __restrict__ kn) {
    int gt = blockIdx.x * blockDim.x + threadIdx.x;
    int w = gt >> 5, lane = gt & 31;
    if (w >= BB) return;
    int eid = exid[w];
    float4 sv = ((const float4*)d_stu)[w * 32 + lane];
    float4 ev = ((const float4*)d_sumA)[(KD + eid) * 32 + lane];
    float4 wa = ((const float4*)fsW)[lane];
    float4 wb = ((const float4*)feW)[lane];
    float ps = sv.x * wa.x + sv.y * wa.y + sv.z * wa.z + sv.w * wa.w;
    float pe = (ev.x * wb.x + ev.y * wb.y + ev.z * wb.z + ev.w * wb.w) * 0.2f;
#pragma unroll
    for (int o = 16; o; o >>= 1) {
        ps += __shfl_xor_sync(0xffffffffu, ps, o);
        pe += __shfl_xor_sync(0xffffffffu, pe, o);
    }
    float ed = 10.f * sigm(disc[eid]);
    float4 cs = ((const float4*)d_cvec)[lane];
    float4 ce = ((const float4*)(d_cvec + KD))[lane];
    float4 kv = ((const float4*)kn)[w * 32 + lane];
    float bs = fsB[0], be = feB[0];
    float4 xo;
    xo.x = ed * (sigm(ps + cs.x + bs) - sigm(pe + ce.x + be)) * kv.x;
    xo.y = ed * (sigm(ps + cs.y + bs) - sigm(pe + ce.y + be)) * kv.y;
    xo.z = ed * (sigm(ps + cs.z + bs) - sigm(pe + ce.z + be)) * kv.z;
    xo.w = ed * (sigm(ps + cs.w + bs) - sigm(pe + ce.w + be)) * kv.w;
    ((float4*)d_x)[w * 32 + lane] = xo;
}

// generic sigmoid-SGEMM: 64x64 tile, 4x4 micro. mode 0: x@W1 -> x1; mode 1: x1@W2 -> x2.
__global__ void __launch_bounds__(256) k_mlp(int mode, const float* __restrict__ Bm,
                                             const float* __restrict__ bias,
                                             int M, int Kc, int Nc) {
    __shared__ float As[16][68];
    __shared__ float Bs[16][64];
    const float* A = (mode == 0) ? d_x : d_x1;
    float* C = (mode == 0) ? d_x1 : d_x2;
    int m0 = blockIdx.x * 64, n0 = blockIdx.y * 64;
    int tid = threadIdx.x;
    int tx = tid & 15, ty = tid >> 4;
    float c[4][4];
#pragma unroll
    for (int i = 0; i < 4; i++)
#pragma unroll
        for (int j = 0; j < 4; j++) c[i][j] = 0.f;

    for (int kt = 0; kt < Kc; kt += 16) {
        for (int i = tid; i < 1024; i += 256) {
            int m = i >> 4, kk = i & 15;
            int mm = m0 + m, kx = kt + kk;
            As[kk][m] = (mm < M && kx < Kc) ? A[mm * Kc + kx] : 0.f;
        }
        for (int i = tid; i < 1024; i += 256) {
            int kk = i >> 6, n = i & 63;
            int nn = n0 + n, kx = kt + kk;
            Bs[kk][n] = (nn < Nc && kx < Kc) ? Bm[kx * Nc + nn] : 0.f;
        }
        __syncthreads();
#pragma unroll
        for (int kk = 0; kk < 16; kk++) {
            float4 a = *(const float4*)&As[kk][ty * 4];
            float4 b = *(const float4*)&Bs[kk][tx * 4];
            float av[4] = {a.x, a.y, a.z, a.w};
            float bv[4] = {b.x, b.y, b.z, b.w};
#pragma unroll
            for (int i = 0; i < 4; i++)
#pragma unroll
                for (int j = 0; j < 4; j++) c[i][j] += av[i] * bv[j];
        }
        __syncthreads();
    }
#pragma unroll
    for (int i = 0; i < 4; i++) {
        int mm = m0 + ty * 4 + i;
        if (mm >= M) continue;
#pragma unroll
        for (int j = 0; j < 4; j++) {
            int nn = n0 + tx * 4 + j;
            if (nn < Nc) C[mm * Nc + nn] = sigm(c[i][j] + bias[nn]);
        }
    }
}

__global__ void k_out(const float* __restrict__ W3, const float* __restrict__ b3,
                      float* __restrict__ out) {
    int gt = blockIdx.x * blockDim.x + threadIdx.x;
    int w = gt >> 5, lane = gt & 31;
    if (w >= BB) return;
    float s = 0.f;
    for (int k = lane; k < H2; k += 32) s += d_x2[w * H2 + k] * W3[k];
#pragma unroll
    for (int o = 16; o; o >>= 1) s += __shfl_xor_sync(0xffffffffu, s, o);
    if (lane == 0) out[w] = sigm(s + b3[0]);
}

// ---------------- launch ----------------
extern "C" void kernel_launch(void* const* d_in, const int* in_sizes, int n_in,
                              void* d_out, int out_size) {
    const float* ent  = (const float*)d_in[0];
    const float* gcnW = (const float*)d_in[1];
    const float* gcnB = (const float*)d_in[2];
    const float* fsW  = (const float*)d_in[3];
    const float* fsB  = (const float*)d_in[4];
    const float* feW  = (const float*)d_in[5];
    const float* feB  = (const float*)d_in[6];
    const float* disc = (const float*)d_in[7];
    const float* W1   = (const float*)d_in[8];
    const float* b1   = (const float*)d_in[9];
    const float* W2   = (const float*)d_in[10];
    const float* b2   = (const float*)d_in[11];
    const float* W3   = (const float*)d_in[12];
    const float* b3   = (const float*)d_in[13];
    const int* ss = (const int*)d_in[14];
    const int* sd = (const int*)d_in[15];
    const int* ps = (const int*)d_in[16];
    const int* pd = (const int*)d_in[17];
    const int* es = (const int*)d_in[18];
    const int* ed = (const int*)d_in[19];
    const int* exid = (const int*)d_in[21];
    const float* kn  = (const float*)d_in[22];
    const int* hid   = (const int*)d_in[23];
    const int* hseg  = (const int*)d_in[24];
    float* out = (float*)d_out;

    k_zero_deg<<<(GN * NN + 255) / 256, 256>>>();
    k_degree<<<(GN * EE + 255) / 256, 256>>>(ss, sd, ps, pd, es, ed);
    k_scan<<<GN, 512>>>();
    k_fill<<<(GN * EE + 255) / 256, 256>>>(ss, sd, ps, pd, es, ed);
    k_init<<<(NN * KD + 255) / 256, 256>>>(ent);

    for (int l = 0; l < 4; l++) {
        k_agg<<<(GN * NN * 32 + 255) / 256, 256>>>(l);
        k_gemm<<<(NN + 127) / 128, 256>>>(gcnW, gcnB, l);
    }

    k_segstart<<<(BB + 1 + 255) / 256, 256>>>(hseg);
    k_stu<<<(BB * 32 + 255) / 256, 256>>>(hid);
    k_cvec<<<1, 256>>>(fsW, feW);
    k_x<<<(BB * 32 + 255) / 256, 256>>>(fsW, fsB, feW, feB, disc, exid, kn);

    dim3 g1((BB + 63) / 64, (H1 + 63) / 64);
    k_mlp<<<g1, 256>>>(0, W1, b1, BB, KD, H1);
    dim3 g2((BB + 63) / 64, (H2 + 63) / 64);
    k_mlp<<<g2, 256>>>(1, W2, b2, BB, KD == 0 ? 0 : H1, H2);
    k_out<<<(BB * 32 + 255) / 256, 256>>>(W3, b3, out);
}

// round 2
// speedup vs baseline: 1.1162x; 1.1162x over previous
#include <cuda_runtime.h>

#define GN 3
constexpr int NN = 16512;     // K + EXER entities  (= 129 * 128 exactly)
constexpr int KD = 128;       // embedding dim
constexpr int EE = 400000;    // edges per graph
constexpr int BB = 4096;      // batch
constexpr int TT = 204800;    // history length
constexpr int H1 = 512;
constexpr int H2 = 216;

// ---------------- scratch (static device globals; no allocation) ----------------
__device__ int   d_deg_s[GN][NN];
__device__ int   d_deg_d[GN][NN];
__device__ int   d_rowp[GN][NN + 1];
__device__ int   d_cur[GN][NN];
__device__ int2  d_csr[GN][EE];     // .x = src idx, .y = norm weight (bits)
__device__ float d_h0[NN * KD];
__device__ float d_h1[NN * KD];
__device__ float d_agg[GN][NN * KD];
__device__ float d_sumA[NN * KD];   // entity_emb + h1+h2+h3+h4  (full = /5)
__device__ float d_sumL[NN * KD];   // h3 + h4                    (disc_full = /2)
__device__ float d_stu[BB * KD];
__device__ int   d_segs[BB + 1];
__device__ float d_cvec[2 * KD];    // [0:128) concept@stuW[K:], [128:256) concept@exeW[K:]
__device__ float d_x[BB * KD];
__device__ float d_x1[BB * H1];
__device__ float d_x2[BB * H2];

__device__ __forceinline__ float sigm(float x) { return 1.f / (1.f + __expf(-x)); }

// ---- packed f32x2 helpers (Blackwell FFMA2 path, PTX-only) ----
__device__ __forceinline__ unsigned long long pack2(float x, float y) {
    unsigned long long r;
    asm("mov.b64 %0, {%1, %2};" : "=l"(r) : "f"(x), "f"(y));
    return r;
}
__device__ __forceinline__ void ffma2(unsigned long long& c, unsigned long long a,
                                      unsigned long long b) {
    asm("fma.rn.f32x2 %0, %1, %2, %0;" : "+l"(c) : "l"(a), "l"(b));
}
__device__ __forceinline__ float2 unpack2(unsigned long long v) {
    float2 r;
    asm("mov.b64 {%0, %1}, %2;" : "=f"(r.x), "=f"(r.y) : "l"(v));
    return r;
}

// ---------------- CSR build ----------------
__global__ void k_zero_deg() {
    int i = blockIdx.x * blockDim.x + threadIdx.x;
    if (i < GN * NN) { ((int*)d_deg_s)[i] = 0; ((int*)d_deg_d)[i] = 0; }
}

__global__ void k_degree(const int* __restrict__ s0, const int* __restrict__ d0,
                         const int* __restrict__ s1, const int* __restrict__ d1,
                         const int* __restrict__ s2, const int* __restrict__ d2) {
    int i = blockIdx.x * blockDim.x + threadIdx.x;
    if (i >= GN * EE) return;
    int g = i / EE, e = i - g * EE;
    const int* S = (g == 0) ? s0 : (g == 1) ? s1 : s2;
    const int* D = (g == 0) ? d0 : (g == 1) ? d1 : d2;
    atomicAdd(&d_deg_s[g][S[e]], 1);
    atomicAdd(&d_deg_d[g][D[e]], 1);
}

// exclusive scan of in-degree -> row_ptr (+cursor copy). one block per graph.
__global__ void k_scan() {
    __shared__ int sA[512], sB[512];
    int g = blockIdx.x, t = threadIdx.x;
    const int CH = (NN + 511) / 512;   // 33
    int base = t * CH;
    int s = 0;
    for (int i = 0; i < CH; i++) { int idx = base + i; if (idx < NN) s += d_deg_d[g][idx]; }
    sA[t] = s;
    __syncthreads();
    int* a = sA; int* b = sB;
    for (int off = 1; off < 512; off <<= 1) {
        b[t] = a[t] + ((t >= off) ? a[t - off] : 0);
        __syncthreads();
        int* tmp = a; a = b; b = tmp;
    }
    int incl = a[t];
    int total = a[511];
    int run = incl - s;
    for (int i = 0; i < CH; i++) {
        int idx = base + i;
        if (idx < NN) { d_rowp[g][idx] = run; d_cur[g][idx] = run; run += d_deg_d[g][idx]; }
    }
    if (t == 0) d_rowp[g][NN] = total;
}

__global__ void k_fill(const int* __restrict__ s0, const int* __restrict__ d0,
                       const int* __restrict__ s1, const int* __restrict__ d1,
                       const int* __restrict__ s2, const int* __restrict__ d2) {
    int i = blockIdx.x * blockDim.x + threadIdx.x;
    if (i >= GN * EE) return;
    int g = i / EE, e = i - g * EE;
    const int* S = (g == 0) ? s0 : (g == 1) ? s1 : s2;
    const int* D = (g == 0) ? d0 : (g == 1) ? d1 : d2;
    int sv = S[e], dv = D[e];
    int pos = atomicAdd(&d_cur[g][dv], 1);
    float a = (float)max(d_deg_s[g][sv], 1);
    float b = (float)max(d_deg_d[g][dv], 1);
    int2 rec;
    rec.x = sv;
    rec.y = __float_as_int(rsqrtf(a * b));
    d_csr[g][pos] = rec;
}

__global__ void k_init(const float* __restrict__ ent) {
    int i = blockIdx.x * blockDim.x + threadIdx.x;
    if (i >= NN * KD) return;
    float v = ent[i];
    d_h0[i] = v;
    d_sumA[i] = v;
    d_sumL[i] = 0.f;
}

// ---------------- GCN layer: aggregation (warp per (g, dst-row)) ----------------
__global__ void __launch_bounds__(256) k_agg(int layer) {
    int gt = blockIdx.x * blockDim.x + threadIdx.x;
    int w = gt >> 5, lane = gt & 31;
    if (w >= GN * NN) return;
    int g = w / NN, n = w - g * NN;
    const float4* __restrict__ hin = (const float4*)((layer & 1) ? d_h1 : d_h0);
    int e0 = d_rowp[g][n], e1 = d_rowp[g][n + 1];
    const int2* __restrict__ cs = d_csr[g];
    float4 a0 = make_float4(0.f, 0.f, 0.f, 0.f);
    float4 a1 = make_float4(0.f, 0.f, 0.f, 0.f);
    int e = e0;
    for (; e + 2 <= e1; e += 2) {
        int2 p0 = cs[e];
        int2 p1 = cs[e + 1];
        float w0 = __int_as_float(p0.y), w1 = __int_as_float(p1.y);
        float4 v0 = hin[p0.x * 32 + lane];
        float4 v1 = hin[p1.x * 32 + lane];
        a0.x += w0 * v0.x; a0.y += w0 * v0.y; a0.z += w0 * v0.z; a0.w += w0 * v0.w;
        a1.x += w1 * v1.x; a1.y += w1 * v1.y; a1.z += w1 * v1.z; a1.w += w1 * v1.w;
    }
    if (e < e1) {
        int2 p = cs[e];
        float wt = __int_as_float(p.y);
        float4 v = hin[p.x * 32 + lane];
        a0.x += wt * v.x; a0.y += wt * v.y; a0.z += wt * v.z; a0.w += wt * v.w;
    }
    float4 acc = make_float4(a0.x + a1.x, a0.y + a1.y, a0.z + a1.z, a0.w + a1.w);
    ((float4*)d_agg[g])[n * 32 + lane] = acc;
}

// ---------------- GCN layer GEMM: h_new = sum_g agg_g @ W_gl + bias_sum
// 128x128 C tile, 256 threads, 8x8 micro via f32x2 FFMA2, BK=16, double-buffered.
__device__ __forceinline__ void gemm_fetch(int kt, int layer, int row0, int tid,
                                           const float* __restrict__ Wg,
                                           float4* pa, float4* pb) {
    int g = kt >> 3;
    int kk0 = (kt & 7) << 4;
    const float* __restrict__ Ag = d_agg[g];
    int r = tid >> 2, kq = (tid & 3) << 2;
    pa[0] = *(const float4*)&Ag[(row0 + r) * KD + kk0 + kq];
    pa[1] = *(const float4*)&Ag[(row0 + r + 64) * KD + kk0 + kq];
    const float* __restrict__ Wb = Wg + ((size_t)((g * 4 + layer) * KD + kk0)) * KD;
    pb[0] = *(const float4*)&Wb[(tid >> 5) * KD + (tid & 31) * 4];
    pb[1] = *(const float4*)&Wb[((tid + 256) >> 5) * KD + (tid & 31) * 4];
}

__device__ __forceinline__ void gemm_store(float (*As)[132], float (*Bs)[128],
                                           int tid, const float4* pa, const float4* pb) {
    int r = tid >> 2, kq = (tid & 3) << 2;
    As[kq + 0][r] = pa[0].x; As[kq + 1][r] = pa[0].y;
    As[kq + 2][r] = pa[0].z; As[kq + 3][r] = pa[0].w;
    As[kq + 0][r + 64] = pa[1].x; As[kq + 1][r + 64] = pa[1].y;
    As[kq + 2][r + 64] = pa[1].z; As[kq + 3][r + 64] = pa[1].w;
    *(float4*)&Bs[tid >> 5][(tid & 31) * 4] = pb[0];
    *(float4*)&Bs[(tid + 256) >> 5][(tid & 31) * 4] = pb[1];
}

__global__ void __launch_bounds__(256) k_gemm(const float* __restrict__ Wg,
                                              const float* __restrict__ bg, int layer) {
    __shared__ float As[2][16][132];
    __shared__ float Bs[2][16][128];
    int row0 = blockIdx.x * 128;
    int tid = threadIdx.x;
    int tx = tid & 15, ty = tid >> 4;

    unsigned long long c2[8][4];
#pragma unroll
    for (int i = 0; i < 8; i++)
#pragma unroll
        for (int j = 0; j < 4; j++) c2[i][j] = 0ull;

    float4 pa[2], pb[2], qa[2], qb[2];
    gemm_fetch(0, layer, row0, tid, Wg, pa, pb);
    gemm_store(As[0], Bs[0], tid, pa, pb);
    __syncthreads();

    for (int kt = 0; kt < 24; kt++) {
        int cur = kt & 1;
        if (kt < 23) gemm_fetch(kt + 1, layer, row0, tid, Wg, qa, qb);
#pragma unroll
        for (int kk = 0; kk < 16; kk++) {
            float4 a0 = *(const float4*)&As[cur][kk][ty * 8];
            float4 a1 = *(const float4*)&As[cur][kk][ty * 8 + 4];
            const unsigned long long* bq =
                (const unsigned long long*)&Bs[cur][kk][tx * 8];
            unsigned long long b0 = bq[0], b1 = bq[1], b2 = bq[2], b3 = bq[3];
            float av[8] = {a0.x, a0.y, a0.z, a0.w, a1.x, a1.y, a1.z, a1.w};
#pragma unroll
            for (int i = 0; i < 8; i++) {
                unsigned long long ai = pack2(av[i], av[i]);
                ffma2(c2[i][0], ai, b0);
                ffma2(c2[i][1], ai, b1);
                ffma2(c2[i][2], ai, b2);
                ffma2(c2[i][3], ai, b3);
            }
        }
        if (kt < 23) gemm_store(As[cur ^ 1], Bs[cur ^ 1], tid, qa, qb);
        __syncthreads();
    }

    float bias[8];
#pragma unroll
    for (int j = 0; j < 8; j++) {
        int col = tx * 8 + j;
        bias[j] = bg[layer * KD + col] + bg[(4 + layer) * KD + col] + bg[(8 + layer) * KD + col];
    }
    float* hout = (layer & 1) ? d_h0 : d_h1;
    bool l2f = (layer >= 2);
#pragma unroll
    for (int i = 0; i < 8; i++) {
        int n = row0 + ty * 8 + i;
        int base = n * KD + tx * 8;
#pragma unroll
        for (int q = 0; q < 2; q++) {
            float2 lo = unpack2(c2[i][2 * q]);
            float2 hi = unpack2(c2[i][2 * q + 1]);
            float4 v;
            v.x = lo.x + bias[q * 4 + 0];
            v.y = lo.y + bias[q * 4 + 1];
            v.z = hi.x + bias[q * 4 + 2];
            v.w = hi.y + bias[q * 4 + 3];
            *(float4*)&hout[base + q * 4] = v;
            float4 sa = *(float4*)&d_sumA[base + q * 4];
            sa.x += v.x; sa.y += v.y; sa.z += v.z; sa.w += v.w;
            *(float4*)&d_sumA[base + q * 4] = sa;
            if (l2f) {
                float4 sl = *(float4*)&d_sumL[base + q * 4];
                sl.x += v.x; sl.y += v.y; sl.z += v.z; sl.w += v.w;
                *(float4*)&d_sumL[base + q * 4] = sl;
            }
        }
    }
}

// ---------------- head ----------------
__global__ void k_segstart(const int* __restrict__ seg) {
    int b = blockIdx.x * blockDim.x + threadIdx.x;
    if (b > BB) return;
    int lo = 0, hi = TT;
    while (lo < hi) { int m = (lo + hi) >> 1; if (seg[m] < b) lo = m + 1; else hi = m; }
    d_segs[b] = lo;
}

// stu[b] = mean over history of disc_full[K+hid]  (disc_full = sumL/2)
__global__ void k_stu(const int* __restrict__ hist) {
    int gt = blockIdx.x * blockDim.x + threadIdx.x;
    int w = gt >> 5, lane = gt & 31;
    if (w >= BB) return;
    int s = d_segs[w], e = d_segs[w + 1];
    const float4* __restrict__ SL = (const float4*)d_sumL;
    float4 acc = make_float4(0.f, 0.f, 0.f, 0.f);
    for (int t = s; t < e; t++) {
        int h = hist[t];
        float4 v = SL[(KD + h) * 32 + lane];
        acc.x += v.x; acc.y += v.y; acc.z += v.z; acc.w += v.w;
    }
    float inv = 0.5f / fmaxf((float)(e - s), 1.f);
    float4 o = make_float4(acc.x * inv, acc.y * inv, acc.z * inv, acc.w * inv);
    ((float4*)d_stu)[w * 32 + lane] = o;
}

// c_stu[j] = (full row j) . stuW[K:],  c_exer[j] = (full row j) . exeW[K:]   (full = sumA/5)
__global__ void k_cvec(const float* __restrict__ stuW, const float* __restrict__ exeW) {
    int tid = threadIdx.x;                  // 256 threads, 1 block
    int j = tid & 127;
    bool isE = tid >= 128;
    const float* wv = isE ? (exeW + KD) : (stuW + KD);
    float s = 0.f;
    for (int k = 0; k < KD; k++) s += d_sumA[j * KD + k] * wv[k];
    d_cvec[(isE ? KD : 0) + j] = s * 0.2f;
}

__global__ void k_x(const float* __restrict__ fsW, const float* __restrict__ fsB,
                    const float* __restrict__ feW, const float* __restrict__ feB,
                    const float* __restrict__ disc, const int* __restrict__ exid,
                    const float* __restrict__ kn) {
    int gt = blockIdx.x * blockDim.x + threadIdx.x;
    int w = gt >> 5, lane = gt & 31;
    if (w >= BB) return;
    int eid = exid[w];
    float4 sv = ((const float4*)d_stu)[w * 32 + lane];
    float4 ev = ((const float4*)d_sumA)[(KD + eid) * 32 + lane];
    float4 wa = ((const float4*)fsW)[lane];
    float4 wb = ((const float4*)feW)[lane];
    float ps = sv.x * wa.x + sv.y * wa.y + sv.z * wa.z + sv.w * wa.w;
    float pe = (ev.x * wb.x + ev.y * wb.y + ev.z * wb.z + ev.w * wb.w) * 0.2f;
#pragma unroll
    for (int o = 16; o; o >>= 1) {
        ps += __shfl_xor_sync(0xffffffffu, ps, o);
        pe += __shfl_xor_sync(0xffffffffu, pe, o);
    }
    float ed = 10.f * sigm(disc[eid]);
    float4 cs = ((const float4*)d_cvec)[lane];
    float4 ce = ((const float4*)(d_cvec + KD))[lane];
    float4 kv = ((const float4*)kn)[w * 32 + lane];
    float bs = fsB[0], be = feB[0];
    float4 xo;
    xo.x = ed * (sigm(ps + cs.x + bs) - sigm(pe + ce.x + be)) * kv.x;
    xo.y = ed * (sigm(ps + cs.y + bs) - sigm(pe + ce.y + be)) * kv.y;
    xo.z = ed * (sigm(ps + cs.z + bs) - sigm(pe + ce.z + be)) * kv.z;
    xo.w = ed * (sigm(ps + cs.w + bs) - sigm(pe + ce.w + be)) * kv.w;
    ((float4*)d_x)[w * 32 + lane] = xo;
}

// generic sigmoid-SGEMM: 64x64 tile, 4x4 micro via f32x2. mode 0: x@W1->x1; mode 1: x1@W2->x2.
__global__ void __launch_bounds__(256) k_mlp(int mode, const float* __restrict__ Bm,
                                             const float* __restrict__ bias,
                                             int M, int Kc, int Nc) {
    __shared__ float As[16][68];
    __shared__ float Bs[16][64];
    const float* __restrict__ A = (mode == 0) ? d_x : d_x1;
    float* C = (mode == 0) ? d_x1 : d_x2;
    int m0 = blockIdx.x * 64, n0 = blockIdx.y * 64;
    int tid = threadIdx.x;
    int tx = tid & 15, ty = tid >> 4;
    unsigned long long c2[4][2];
#pragma unroll
    for (int i = 0; i < 4; i++) { c2[i][0] = 0ull; c2[i][1] = 0ull; }

    for (int kt = 0; kt < Kc; kt += 16) {
        for (int i = tid; i < 1024; i += 256) {
            int m = i >> 4, kk = i & 15;
            As[kk][m] = A[(m0 + m) * Kc + kt + kk];
        }
        for (int i = tid; i < 1024; i += 256) {
            int kk = i >> 6, n = i & 63;
            int nn = n0 + n;
            Bs[kk][n] = (nn < Nc) ? Bm[(kt + kk) * Nc + nn] : 0.f;
        }
        __syncthreads();
#pragma unroll
        for (int kk = 0; kk < 16; kk++) {
            float4 a = *(const float4*)&As[kk][ty * 4];
            const unsigned long long* bq = (const unsigned long long*)&Bs[kk][tx * 4];
            unsigned long long b0 = bq[0], b1 = bq[1];
            float av[4] = {a.x, a.y, a.z, a.w};
#pragma unroll
            for (int i = 0; i < 4; i++) {
                unsigned long long ai = pack2(av[i], av[i]);
                ffma2(c2[i][0], ai, b0);
                ffma2(c2[i][1], ai, b1);
            }
        }
        __syncthreads();
    }
#pragma unroll
    for (int i = 0; i < 4; i++) {
        int mm = m0 + ty * 4 + i;
        float2 lo = unpack2(c2[i][0]);
        float2 hi = unpack2(c2[i][1]);
        float cv[4] = {lo.x, lo.y, hi.x, hi.y};
#pragma unroll
        for (int j = 0; j < 4; j++) {
            int nn = n0 + tx * 4 + j;
            if (nn < Nc) C[mm * Nc + nn] = sigm(cv[j] + bias[nn]);
        }
    }
}

__global__ void k_out(const float* __restrict__ W3, const float* __restrict__ b3,
                      float* __restrict__ out) {
    int gt = blockIdx.x * blockDim.x + threadIdx.x;
    int w = gt >> 5, lane = gt & 31;
    if (w >= BB) return;
    float s = 0.f;
    for (int k = lane; k < H2; k += 32) s += d_x2[w * H2 + k] * W3[k];
#pragma unroll
    for (int o = 16; o; o >>= 1) s += __shfl_xor_sync(0xffffffffu, s, o);
    if (lane == 0) out[w] = sigm(s + b3[0]);
}

// ---------------- launch ----------------
extern "C" void kernel_launch(void* const* d_in, const int* in_sizes, int n_in,
                              void* d_out, int out_size) {
    const float* ent  = (const float*)d_in[0];
    const float* gcnW = (const float*)d_in[1];
    const float* gcnB = (const float*)d_in[2];
    const float* fsW  = (const float*)d_in[3];
    const float* fsB  = (const float*)d_in[4];
    const float* feW  = (const float*)d_in[5];
    const float* feB  = (const float*)d_in[6];
    const float* disc = (const float*)d_in[7];
    const float* W1   = (const float*)d_in[8];
    const float* b1   = (const float*)d_in[9];
    const float* W2   = (const float*)d_in[10];
    const float* b2   = (const float*)d_in[11];
    const float* W3   = (const float*)d_in[12];
    const float* b3   = (const float*)d_in[13];
    const int* ss = (const int*)d_in[14];
    const int* sd = (const int*)d_in[15];
    const int* ps = (const int*)d_in[16];
    const int* pd = (const int*)d_in[17];
    const int* es = (const int*)d_in[18];
    const int* ed = (const int*)d_in[19];
    const int* exid = (const int*)d_in[21];
    const float* kn  = (const float*)d_in[22];
    const int* hid   = (const int*)d_in[23];
    const int* hseg  = (const int*)d_in[24];
    float* out = (float*)d_out;

    k_zero_deg<<<(GN * NN + 255) / 256, 256>>>();
    k_degree<<<(GN * EE + 255) / 256, 256>>>(ss, sd, ps, pd, es, ed);
    k_scan<<<GN, 512>>>();
    k_fill<<<(GN * EE + 255) / 256, 256>>>(ss, sd, ps, pd, es, ed);
    k_init<<<(NN * KD + 255) / 256, 256>>>(ent);

    for (int l = 0; l < 4; l++) {
        k_agg<<<(GN * NN * 32 + 255) / 256, 256>>>(l);
        k_gemm<<<NN / 128, 256>>>(gcnW, gcnB, l);
    }

    k_segstart<<<(BB + 1 + 255) / 256, 256>>>(hseg);
    k_stu<<<(BB * 32 + 255) / 256, 256>>>(hid);
    k_cvec<<<1, 256>>>(fsW, feW);
    k_x<<<(BB * 32 + 255) / 256, 256>>>(fsW, fsB, feW, feB, disc, exid, kn);

    dim3 g1((BB + 63) / 64, (H1 + 63) / 64);
    k_mlp<<<g1, 256>>>(0, W1, b1, BB, KD, H1);
    dim3 g2((BB + 63) / 64, (H2 + 63) / 64);
    k_mlp<<<g2, 256>>>(1, W2, b2, BB, H1, H2);
    k_out<<<(BB * 32 + 255) / 256, 256>>>(W3, b3, out);
}

// round 3
// speedup vs baseline: 1.2246x; 1.0971x over previous
#include <cuda_runtime.h>
#include <cuda_fp16.h>

#define GN 3
constexpr int NN = 16512;     // K + EXER entities  (= 129 * 128 exactly)
constexpr int KD = 128;       // embedding dim
constexpr int EE = 400000;    // edges per graph (divisible by 4)
constexpr int BB = 4096;      // batch
constexpr int TT = 204800;    // history length
constexpr int H1 = 512;
constexpr int H2 = 216;

// ---------------- scratch (static device globals; no allocation) ----------------
__device__ int    d_deg_s[GN][NN];
__device__ int    d_deg_d[GN][NN];
__device__ int    d_rowp[GN][NN + 1];
__device__ int    d_cur[GN][NN];
__device__ int2   d_csr[GN][EE];     // .x = src idx, .y = norm weight (bits)
__device__ __half d_hh0[NN * KD];    // fp16 activations (gather source)
__device__ __half d_hh1[NN * KD];
__device__ float  d_agg[GN][NN * KD];
__device__ float  d_sumA[NN * KD];   // entity_emb + h1+h2+h3+h4  (full = /5)
__device__ float  d_sumL[NN * KD];   // h3 + h4                    (disc_full = /2)
__device__ float  d_stu[BB * KD];
__device__ int    d_segs[BB + 1];
__device__ float  d_cvec[2 * KD];
__device__ float  d_x[BB * KD];
__device__ float  d_x1[BB * H1];
__device__ float  d_x2[BB * H2];

__device__ __forceinline__ float sigm(float x) { return 1.f / (1.f + __expf(-x)); }

// ---- packed f32x2 helpers (Blackwell FFMA2 path, PTX-only) ----
__device__ __forceinline__ unsigned long long pack2(float x, float y) {
    unsigned long long r;
    asm("mov.b64 %0, {%1, %2};" : "=l"(r) : "f"(x), "f"(y));
    return r;
}
__device__ __forceinline__ void ffma2(unsigned long long& c, unsigned long long a,
                                      unsigned long long b) {
    asm("fma.rn.f32x2 %0, %1, %2, %0;" : "+l"(c) : "l"(a), "l"(b));
}
__device__ __forceinline__ float2 unpack2(unsigned long long v) {
    float2 r;
    asm("mov.b64 {%0, %1}, %2;" : "=f"(r.x), "=f"(r.y) : "l"(v));
    return r;
}

// ---------------- CSR build ----------------
__global__ void k_zero_deg() {
    int i = blockIdx.x * blockDim.x + threadIdx.x;
    if (i < GN * NN) { ((int*)d_deg_s)[i] = 0; ((int*)d_deg_d)[i] = 0; }
}

// 4 edges per thread -> MLP=4 on the L2 atomics
__global__ void k_degree(const int* __restrict__ s0, const int* __restrict__ d0,
                         const int* __restrict__ s1, const int* __restrict__ d1,
                         const int* __restrict__ s2, const int* __restrict__ d2) {
    int i = blockIdx.x * blockDim.x + threadIdx.x;
    const int Q = EE / 4;
    if (i >= GN * Q) return;
    int g = i / Q, e4 = (i - g * Q) * 4;
    const int* S = (g == 0) ? s0 : (g == 1) ? s1 : s2;
    const int* D = (g == 0) ? d0 : (g == 1) ? d1 : d2;
    int4 sv = *(const int4*)&S[e4];
    int4 dv = *(const int4*)&D[e4];
    atomicAdd(&d_deg_s[g][sv.x], 1); atomicAdd(&d_deg_s[g][sv.y], 1);
    atomicAdd(&d_deg_s[g][sv.z], 1); atomicAdd(&d_deg_s[g][sv.w], 1);
    atomicAdd(&d_deg_d[g][dv.x], 1); atomicAdd(&d_deg_d[g][dv.y], 1);
    atomicAdd(&d_deg_d[g][dv.z], 1); atomicAdd(&d_deg_d[g][dv.w], 1);
}

// exclusive scan of in-degree -> row_ptr (+cursor copy). one block per graph.
__global__ void k_scan() {
    __shared__ int sA[512], sB[512];
    int g = blockIdx.x, t = threadIdx.x;
    const int CH = (NN + 511) / 512;   // 33
    int base = t * CH;
    int s = 0;
    for (int i = 0; i < CH; i++) { int idx = base + i; if (idx < NN) s += d_deg_d[g][idx]; }
    sA[t] = s;
    __syncthreads();
    int* a = sA; int* b = sB;
    for (int off = 1; off < 512; off <<= 1) {
        b[t] = a[t] + ((t >= off) ? a[t - off] : 0);
        __syncthreads();
        int* tmp = a; a = b; b = tmp;
    }
    int incl = a[t];
    int total = a[511];
    int run = incl - s;
    for (int i = 0; i < CH; i++) {
        int idx = base + i;
        if (idx < NN) { d_rowp[g][idx] = run; d_cur[g][idx] = run; run += d_deg_d[g][idx]; }
    }
    if (t == 0) d_rowp[g][NN] = total;
}

// 4 edges per thread
__global__ void k_fill(const int* __restrict__ s0, const int* __restrict__ d0,
                       const int* __restrict__ s1, const int* __restrict__ d1,
                       const int* __restrict__ s2, const int* __restrict__ d2) {
    int i = blockIdx.x * blockDim.x + threadIdx.x;
    const int Q = EE / 4;
    if (i >= GN * Q) return;
    int g = i / Q, e4 = (i - g * Q) * 4;
    const int* S = (g == 0) ? s0 : (g == 1) ? s1 : s2;
    const int* D = (g == 0) ? d0 : (g == 1) ? d1 : d2;
    int4 sv = *(const int4*)&S[e4];
    int4 dv = *(const int4*)&D[e4];
    int ds0 = d_deg_s[g][sv.x], ds1 = d_deg_s[g][sv.y];
    int ds2 = d_deg_s[g][sv.z], ds3 = d_deg_s[g][sv.w];
    int dd0 = d_deg_d[g][dv.x], dd1 = d_deg_d[g][dv.y];
    int dd2 = d_deg_d[g][dv.z], dd3 = d_deg_d[g][dv.w];
    int p0 = atomicAdd(&d_cur[g][dv.x], 1);
    int p1 = atomicAdd(&d_cur[g][dv.y], 1);
    int p2 = atomicAdd(&d_cur[g][dv.z], 1);
    int p3 = atomicAdd(&d_cur[g][dv.w], 1);
    int2 r0, r1, r2, r3;
    r0.x = sv.x; r0.y = __float_as_int(rsqrtf((float)max(ds0, 1) * (float)max(dd0, 1)));
    r1.x = sv.y; r1.y = __float_as_int(rsqrtf((float)max(ds1, 1) * (float)max(dd1, 1)));
    r2.x = sv.z; r2.y = __float_as_int(rsqrtf((float)max(ds2, 1) * (float)max(dd2, 1)));
    r3.x = sv.w; r3.y = __float_as_int(rsqrtf((float)max(ds3, 1) * (float)max(dd3, 1)));
    d_csr[g][p0] = r0; d_csr[g][p1] = r1; d_csr[g][p2] = r2; d_csr[g][p3] = r3;
}

__global__ void k_init(const float* __restrict__ ent) {
    int i = blockIdx.x * blockDim.x + threadIdx.x;
    if (i >= NN * KD) return;
    float v = ent[i];
    d_hh0[i] = __float2half_rn(v);
    d_sumA[i] = v;
    d_sumL[i] = 0.f;
}

// ---------------- GCN layer: aggregation (warp per (g, dst-row)), fp16 gather ----
__global__ void __launch_bounds__(256) k_agg(int layer) {
    int gt = blockIdx.x * blockDim.x + threadIdx.x;
    int w = gt >> 5, lane = gt & 31;
    if (w >= GN * NN) return;
    int g = w / NN, n = w - g * NN;
    const __half* __restrict__ hin = (layer & 1) ? d_hh1 : d_hh0;
    int e0 = d_rowp[g][n], e1 = d_rowp[g][n + 1];
    const int2* __restrict__ cs = d_csr[g];
    int col = lane * 4;
    float a0x = 0.f, a0y = 0.f, a0z = 0.f, a0w = 0.f;
    float a1x = 0.f, a1y = 0.f, a1z = 0.f, a1w = 0.f;
    int e = e0;
    for (; e + 4 <= e1; e += 4) {
        int2 p0 = cs[e], p1 = cs[e + 1], p2 = cs[e + 2], p3 = cs[e + 3];
        uint2 r0 = *(const uint2*)(hin + p0.x * KD + col);
        uint2 r1 = *(const uint2*)(hin + p1.x * KD + col);
        uint2 r2 = *(const uint2*)(hin + p2.x * KD + col);
        uint2 r3 = *(const uint2*)(hin + p3.x * KD + col);
        float w0 = __int_as_float(p0.y), w1 = __int_as_float(p1.y);
        float w2 = __int_as_float(p2.y), w3 = __int_as_float(p3.y);
        float2 f;
        f = __half22float2(*(__half2*)&r0.x); a0x += w0 * f.x; a0y += w0 * f.y;
        f = __half22float2(*(__half2*)&r0.y); a0z += w0 * f.x; a0w += w0 * f.y;
        f = __half22float2(*(__half2*)&r1.x); a1x += w1 * f.x; a1y += w1 * f.y;
        f = __half22float2(*(__half2*)&r1.y); a1z += w1 * f.x; a1w += w1 * f.y;
        f = __half22float2(*(__half2*)&r2.x); a0x += w2 * f.x; a0y += w2 * f.y;
        f = __half22float2(*(__half2*)&r2.y); a0z += w2 * f.x; a0w += w2 * f.y;
        f = __half22float2(*(__half2*)&r3.x); a1x += w3 * f.x; a1y += w3 * f.y;
        f = __half22float2(*(__half2*)&r3.y); a1z += w3 * f.x; a1w += w3 * f.y;
    }
    for (; e < e1; e++) {
        int2 p = cs[e];
        uint2 r = *(const uint2*)(hin + p.x * KD + col);
        float wt = __int_as_float(p.y);
        float2 f;
        f = __half22float2(*(__half2*)&r.x); a0x += wt * f.x; a0y += wt * f.y;
        f = __half22float2(*(__half2*)&r.y); a0z += wt * f.x; a0w += wt * f.y;
    }
    float4 acc = make_float4(a0x + a1x, a0y + a1y, a0z + a1z, a0w + a1w);
    *(float4*)&d_agg[g][n * KD + col] = acc;
}

// ---------------- GCN layer GEMM: h_new = sum_g agg_g @ W_gl + bias_sum
// 128x128 C tile, 256 threads, 8x8 micro via f32x2 FFMA2, BK=16, double-buffered.
__device__ __forceinline__ void gemm_fetch(int kt, int layer, int row0, int tid,
                                           const float* __restrict__ Wg,
                                           float4* pa, float4* pb) {
    int g = kt >> 3;
    int kk0 = (kt & 7) << 4;
    const float* __restrict__ Ag = d_agg[g];
    int r = tid >> 2, kq = (tid & 3) << 2;
    pa[0] = *(const float4*)&Ag[(row0 + r) * KD + kk0 + kq];
    pa[1] = *(const float4*)&Ag[(row0 + r + 64) * KD + kk0 + kq];
    const float* __restrict__ Wb = Wg + ((size_t)((g * 4 + layer) * KD + kk0)) * KD;
    pb[0] = *(const float4*)&Wb[(tid >> 5) * KD + (tid & 31) * 4];
    pb[1] = *(const float4*)&Wb[((tid + 256) >> 5) * KD + (tid & 31) * 4];
}

__device__ __forceinline__ void gemm_store(float (*As)[132], float (*Bs)[128],
                                           int tid, const float4* pa, const float4* pb) {
    int r = tid >> 2, kq = (tid & 3) << 2;
    As[kq + 0][r] = pa[0].x; As[kq + 1][r] = pa[0].y;
    As[kq + 2][r] = pa[0].z; As[kq + 3][r] = pa[0].w;
    As[kq + 0][r + 64] = pa[1].x; As[kq + 1][r + 64] = pa[1].y;
    As[kq + 2][r + 64] = pa[1].z; As[kq + 3][r + 64] = pa[1].w;
    *(float4*)&Bs[tid >> 5][(tid & 31) * 4] = pb[0];
    *(float4*)&Bs[(tid + 256) >> 5][(tid & 31) * 4] = pb[1];
}

__global__ void __launch_bounds__(256) k_gemm(const float* __restrict__ Wg,
                                              const float* __restrict__ bg, int layer) {
    __shared__ float As[2][16][132];
    __shared__ float Bs[2][16][128];
    int row0 = blockIdx.x * 128;
    int tid = threadIdx.x;
    int tx = tid & 15, ty = tid >> 4;

    unsigned long long c2[8][4];
#pragma unroll
    for (int i = 0; i < 8; i++)
#pragma unroll
        for (int j = 0; j < 4; j++) c2[i][j] = 0ull;

    float4 pa[2], pb[2], qa[2], qb[2];
    gemm_fetch(0, layer, row0, tid, Wg, pa, pb);
    gemm_store(As[0], Bs[0], tid, pa, pb);
    __syncthreads();

    for (int kt = 0; kt < 24; kt++) {
        int cur = kt & 1;
        if (kt < 23) gemm_fetch(kt + 1, layer, row0, tid, Wg, qa, qb);
#pragma unroll
        for (int kk = 0; kk < 16; kk++) {
            float4 a0 = *(const float4*)&As[cur][kk][ty * 8];
            float4 a1 = *(const float4*)&As[cur][kk][ty * 8 + 4];
            const unsigned long long* bq =
                (const unsigned long long*)&Bs[cur][kk][tx * 8];
            unsigned long long b0 = bq[0], b1 = bq[1], b2 = bq[2], b3 = bq[3];
            float av[8] = {a0.x, a0.y, a0.z, a0.w, a1.x, a1.y, a1.z, a1.w};
#pragma unroll
            for (int i = 0; i < 8; i++) {
                unsigned long long ai = pack2(av[i], av[i]);
                ffma2(c2[i][0], ai, b0);
                ffma2(c2[i][1], ai, b1);
                ffma2(c2[i][2], ai, b2);
                ffma2(c2[i][3], ai, b3);
            }
        }
        if (kt < 23) gemm_store(As[cur ^ 1], Bs[cur ^ 1], tid, qa, qb);
        __syncthreads();
    }

    float bias[8];
#pragma unroll
    for (int j = 0; j < 8; j++) {
        int col = tx * 8 + j;
        bias[j] = bg[layer * KD + col] + bg[(4 + layer) * KD + col] + bg[(8 + layer) * KD + col];
    }
    __half* hout = (layer & 1) ? d_hh0 : d_hh1;
    bool l2f = (layer >= 2);
#pragma unroll
    for (int i = 0; i < 8; i++) {
        int n = row0 + ty * 8 + i;
        int base = n * KD + tx * 8;
#pragma unroll
        for (int q = 0; q < 2; q++) {
            float2 lo = unpack2(c2[i][2 * q]);
            float2 hi = unpack2(c2[i][2 * q + 1]);
            float4 v;
            v.x = lo.x + bias[q * 4 + 0];
            v.y = lo.y + bias[q * 4 + 1];
            v.z = hi.x + bias[q * 4 + 2];
            v.w = hi.y + bias[q * 4 + 3];
            __half2 h01 = __floats2half2_rn(v.x, v.y);
            __half2 h23 = __floats2half2_rn(v.z, v.w);
            uint2 hv;
            hv.x = *(unsigned*)&h01;
            hv.y = *(unsigned*)&h23;
            *(uint2*)&hout[base + q * 4] = hv;
            float4 sa = *(float4*)&d_sumA[base + q * 4];
            sa.x += v.x; sa.y += v.y; sa.z += v.z; sa.w += v.w;
            *(float4*)&d_sumA[base + q * 4] = sa;
            if (l2f) {
                float4 sl = *(float4*)&d_sumL[base + q * 4];
                sl.x += v.x; sl.y += v.y; sl.z += v.z; sl.w += v.w;
                *(float4*)&d_sumL[base + q * 4] = sl;
            }
        }
    }
}

// ---------------- head ----------------
__global__ void k_segstart(const int* __restrict__ seg) {
    int b = blockIdx.x * blockDim.x + threadIdx.x;
    if (b > BB) return;
    int lo = 0, hi = TT;
    while (lo < hi) { int m = (lo + hi) >> 1; if (seg[m] < b) lo = m + 1; else hi = m; }
    d_segs[b] = lo;
}

// stu[b] = mean over history of disc_full[K+hid]  (disc_full = sumL/2)
__global__ void k_stu(const int* __restrict__ hist) {
    int gt = blockIdx.x * blockDim.x + threadIdx.x;
    int w = gt >> 5, lane = gt & 31;
    if (w >= BB) return;
    int s = d_segs[w], e = d_segs[w + 1];
    const float4* __restrict__ SL = (const float4*)d_sumL;
    float4 acc = make_float4(0.f, 0.f, 0.f, 0.f);
    for (int t = s; t < e; t++) {
        int h = hist[t];
        float4 v = SL[(KD + h) * 32 + lane];
        acc.x += v.x; acc.y += v.y; acc.z += v.z; acc.w += v.w;
    }
    float inv = 0.5f / fmaxf((float)(e - s), 1.f);
    float4 o = make_float4(acc.x * inv, acc.y * inv, acc.z * inv, acc.w * inv);
    ((float4*)d_stu)[w * 32 + lane] = o;
}

// c_stu[j] = (full row j) . stuW[K:],  c_exer[j] = (full row j) . exeW[K:]   (full = sumA/5)
__global__ void k_cvec(const float* __restrict__ stuW, const float* __restrict__ exeW) {
    int tid = threadIdx.x;                  // 256 threads, 1 block
    int j = tid & 127;
    bool isE = tid >= 128;
    const float* wv = isE ? (exeW + KD) : (stuW + KD);
    float s = 0.f;
    for (int k = 0; k < KD; k++) s += d_sumA[j * KD + k] * wv[k];
    d_cvec[(isE ? KD : 0) + j] = s * 0.2f;
}

__global__ void k_x(const float* __restrict__ fsW, const float* __restrict__ fsB,
                    const float* __restrict__ feW, const float* __restrict__ feB,
                    const float* __restrict__ disc, const int* __restrict__ exid,
                    const float* __restrict__ kn) {
    int gt = blockIdx.x * blockDim.x + threadIdx.x;
    int w = gt >> 5, lane = gt & 31;
    if (w >= BB) return;
    int eid = exid[w];
    float4 sv = ((const float4*)d_stu)[w * 32 + lane];
    float4 ev = ((const float4*)d_sumA)[(KD + eid) * 32 + lane];
    float4 wa = ((const float4*)fsW)[lane];
    float4 wb = ((const float4*)feW)[lane];
    float ps = sv.x * wa.x + sv.y * wa.y + sv.z * wa.z + sv.w * wa.w;
    float pe = (ev.x * wb.x + ev.y * wb.y + ev.z * wb.z + ev.w * wb.w) * 0.2f;
#pragma unroll
    for (int o = 16; o; o >>= 1) {
        ps += __shfl_xor_sync(0xffffffffu, ps, o);
        pe += __shfl_xor_sync(0xffffffffu, pe, o);
    }
    float ed = 10.f * sigm(disc[eid]);
    float4 cs = ((const float4*)d_cvec)[lane];
    float4 ce = ((const float4*)(d_cvec + KD))[lane];
    float4 kv = ((const float4*)kn)[w * 32 + lane];
    float bs = fsB[0], be = feB[0];
    float4 xo;
    xo.x = ed * (sigm(ps + cs.x + bs) - sigm(pe + ce.x + be)) * kv.x;
    xo.y = ed * (sigm(ps + cs.y + bs) - sigm(pe + ce.y + be)) * kv.y;
    xo.z = ed * (sigm(ps + cs.z + bs) - sigm(pe + ce.z + be)) * kv.z;
    xo.w = ed * (sigm(ps + cs.w + bs) - sigm(pe + ce.w + be)) * kv.w;
    ((float4*)d_x)[w * 32 + lane] = xo;
}

// generic sigmoid-SGEMM: 64x64 tile, 4x4 micro via f32x2. mode 0: x@W1->x1; mode 1: x1@W2->x2.
__global__ void __launch_bounds__(256) k_mlp(int mode, const float* __restrict__ Bm,
                                             const float* __restrict__ bias,
                                             int M, int Kc, int Nc) {
    __shared__ float As[16][68];
    __shared__ float Bs[16][64];
    const float* __restrict__ A = (mode == 0) ? d_x : d_x1;
    float* C = (mode == 0) ? d_x1 : d_x2;
    int m0 = blockIdx.x * 64, n0 = blockIdx.y * 64;
    int tid = threadIdx.x;
    int tx = tid & 15, ty = tid >> 4;
    unsigned long long c2[4][2];
#pragma unroll
    for (int i = 0; i < 4; i++) { c2[i][0] = 0ull; c2[i][1] = 0ull; }

    for (int kt = 0; kt < Kc; kt += 16) {
        for (int i = tid; i < 1024; i += 256) {
            int m = i >> 4, kk = i & 15;
            As[kk][m] = A[(m0 + m) * Kc + kt + kk];
        }
        for (int i = tid; i < 1024; i += 256) {
            int kk = i >> 6, n = i & 63;
            int nn = n0 + n;
            Bs[kk][n] = (nn < Nc) ? Bm[(kt + kk) * Nc + nn] : 0.f;
        }
        __syncthreads();
#pragma unroll
        for (int kk = 0; kk < 16; kk++) {
            float4 a = *(const float4*)&As[kk][ty * 4];
            const unsigned long long* bq = (const unsigned long long*)&Bs[kk][tx * 4];
            unsigned long long b0 = bq[0], b1 = bq[1];
            float av[4] = {a.x, a.y, a.z, a.w};
#pragma unroll
            for (int i = 0; i < 4; i++) {
                unsigned long long ai = pack2(av[i], av[i]);
                ffma2(c2[i][0], ai, b0);
                ffma2(c2[i][1], ai, b1);
            }
        }
        __syncthreads();
    }
#pragma unroll
    for (int i = 0; i < 4; i++) {
        int mm = m0 + ty * 4 + i;
        float2 lo = unpack2(c2[i][0]);
        float2 hi = unpack2(c2[i][1]);
        float cv[4] = {lo.x, lo.y, hi.x, hi.y};
#pragma unroll
        for (int j = 0; j < 4; j++) {
            int nn = n0 + tx * 4 + j;
            if (nn < Nc) C[mm * Nc + nn] = sigm(cv[j] + bias[nn]);
        }
    }
}

__global__ void k_out(const float* __restrict__ W3, const float* __restrict__ b3,
                      float* __restrict__ out) {
    int gt = blockIdx.x * blockDim.x + threadIdx.x;
    int w = gt >> 5, lane = gt & 31;
    if (w >= BB) return;
    float s = 0.f;
    for (int k = lane; k < H2; k += 32) s += d_x2[w * H2 + k] * W3[k];
#pragma unroll
    for (int o = 16; o; o >>= 1) s += __shfl_xor_sync(0xffffffffu, s, o);
    if (lane == 0) out[w] = sigm(s + b3[0]);
}

// ---------------- launch ----------------
extern "C" void kernel_launch(void* const* d_in, const int* in_sizes, int n_in,
                              void* d_out, int out_size) {
    const float* ent  = (const float*)d_in[0];
    const float* gcnW = (const float*)d_in[1];
    const float* gcnB = (const float*)d_in[2];
    const float* fsW  = (const float*)d_in[3];
    const float* fsB  = (const float*)d_in[4];
    const float* feW  = (const float*)d_in[5];
    const float* feB  = (const float*)d_in[6];
    const float* disc = (const float*)d_in[7];
    const float* W1   = (const float*)d_in[8];
    const float* b1   = (const float*)d_in[9];
    const float* W2   = (const float*)d_in[10];
    const float* b2   = (const float*)d_in[11];
    const float* W3   = (const float*)d_in[12];
    const float* b3   = (const float*)d_in[13];
    const int* ss = (const int*)d_in[14];
    const int* sd = (const int*)d_in[15];
    const int* ps = (const int*)d_in[16];
    const int* pd = (const int*)d_in[17];
    const int* es = (const int*)d_in[18];
    const int* ed = (const int*)d_in[19];
    const int* exid = (const int*)d_in[21];
    const float* kn  = (const float*)d_in[22];
    const int* hid   = (const int*)d_in[23];
    const int* hseg  = (const int*)d_in[24];
    float* out = (float*)d_out;

    k_zero_deg<<<(GN * NN + 255) / 256, 256>>>();
    k_degree<<<(GN * (EE / 4) + 255) / 256, 256>>>(ss, sd, ps, pd, es, ed);
    k_scan<<<GN, 512>>>();
    k_fill<<<(GN * (EE / 4) + 255) / 256, 256>>>(ss, sd, ps, pd, es, ed);
    k_init<<<(NN * KD + 255) / 256, 256>>>(ent);

    for (int l = 0; l < 4; l++) {
        k_agg<<<(GN * NN * 32 + 255) / 256, 256>>>(l);
        k_gemm<<<NN / 128, 256>>>(gcnW, gcnB, l);
    }

    k_segstart<<<(BB + 1 + 255) / 256, 256>>>(hseg);
    k_stu<<<(BB * 32 + 255) / 256, 256>>>(hid);
    k_cvec<<<1, 256>>>(fsW, feW);
    k_x<<<(BB * 32 + 255) / 256, 256>>>(fsW, fsB, feW, feB, disc, exid, kn);

    dim3 g1((BB + 63) / 64, (H1 + 63) / 64);
    k_mlp<<<g1, 256>>>(0, W1, b1, BB, KD, H1);
    dim3 g2((BB + 63) / 64, (H2 + 63) / 64);
    k_mlp<<<g2, 256>>>(1, W2, b2, BB, H1, H2);
    k_out<<<(BB * 32 + 255) / 256, 256>>>(W3, b3, out);
}

// round 4
// speedup vs baseline: 1.4978x; 1.2231x over previous
#include <cuda_runtime.h>
#include <cuda_fp16.h>
#include <mma.h>

using namespace nvcuda;

#define GN 3
constexpr int NN = 16512;     // K + EXER entities  (= 129 * 128 exactly)
constexpr int KD = 128;       // embedding dim
constexpr int EE = 400000;    // edges per graph (divisible by 4)
constexpr int BB = 4096;      // batch
constexpr int TT = 204800;    // history length
constexpr int H1 = 512;
constexpr int H2 = 216;
constexpr int H2P = 224;      // padded to 14*16

// ---------------- scratch (static device globals; no allocation) ----------------
__device__ int    d_deg_s[GN][NN];
__device__ int    d_deg_d[GN][NN];
__device__ int    d_rowp[GN][NN + 1];
__device__ int    d_cur[GN][NN];
__device__ int2   d_csr[GN][EE];     // .x = src idx, .y = norm weight (bits)
__device__ __half d_hh0[NN * KD];    // fp16 activations (gather source)
__device__ __half d_hh1[NN * KD];
__device__ __half d_aggh[GN][NN * KD];   // fp16 aggregation output (A for tensor GEMM)
__device__ __half d_Wh[GN * 4 * KD * KD];// fp16 GCN weights [g][l][k][n]
__device__ float  d_biasC[4][KD];        // per-layer combined bias (sum over g)
__device__ __half d_W1h[KD * H1];
__device__ __half d_W2h[H1 * H2P];       // zero-padded cols
__device__ float  d_sumA[NN * KD];   // entity_emb + h1+h2+h3+h4  (full = /5)
__device__ float  d_sumL[NN * KD];   // h3 + h4                    (disc_full = /2)
__device__ float  d_stu[BB * KD];
__device__ int    d_segs[BB + 1];
__device__ float  d_cvec[2 * KD];
__device__ __half d_xh[BB * KD];
__device__ __half d_x1h[BB * H1];
__device__ float  d_x2[BB * H2];

__device__ __forceinline__ float sigm(float x) { return 1.f / (1.f + __expf(-x)); }

// ---------------- CSR build ----------------
__global__ void k_zero_deg() {
    int i = blockIdx.x * blockDim.x + threadIdx.x;
    if (i < GN * NN) { ((int*)d_deg_s)[i] = 0; ((int*)d_deg_d)[i] = 0; }
}

// 4 edges per thread -> MLP=4 on the L2 atomics
__global__ void k_degree(const int* __restrict__ s0, const int* __restrict__ d0,
                         const int* __restrict__ s1, const int* __restrict__ d1,
                         const int* __restrict__ s2, const int* __restrict__ d2) {
    int i = blockIdx.x * blockDim.x + threadIdx.x;
    const int Q = EE / 4;
    if (i >= GN * Q) return;
    int g = i / Q, e4 = (i - g * Q) * 4;
    const int* S = (g == 0) ? s0 : (g == 1) ? s1 : s2;
    const int* D = (g == 0) ? d0 : (g == 1) ? d1 : d2;
    int4 sv = *(const int4*)&S[e4];
    int4 dv = *(const int4*)&D[e4];
    atomicAdd(&d_deg_s[g][sv.x], 1); atomicAdd(&d_deg_s[g][sv.y], 1);
    atomicAdd(&d_deg_s[g][sv.z], 1); atomicAdd(&d_deg_s[g][sv.w], 1);
    atomicAdd(&d_deg_d[g][dv.x], 1); atomicAdd(&d_deg_d[g][dv.y], 1);
    atomicAdd(&d_deg_d[g][dv.z], 1); atomicAdd(&d_deg_d[g][dv.w], 1);
}

// exclusive scan of in-degree -> row_ptr (+cursor copy). one block per graph.
__global__ void k_scan() {
    __shared__ int sA[512], sB[512];
    int g = blockIdx.x, t = threadIdx.x;
    const int CH = (NN + 511) / 512;   // 33
    int base = t * CH;
    int s = 0;
    for (int i = 0; i < CH; i++) { int idx = base + i; if (idx < NN) s += d_deg_d[g][idx]; }
    sA[t] = s;
    __syncthreads();
    int* a = sA; int* b = sB;
    for (int off = 1; off < 512; off <<= 1) {
        b[t] = a[t] + ((t >= off) ? a[t - off] : 0);
        __syncthreads();
        int* tmp = a; a = b; b = tmp;
    }
    int incl = a[t];
    int total = a[511];
    int run = incl - s;
    for (int i = 0; i < CH; i++) {
        int idx = base + i;
        if (idx < NN) { d_rowp[g][idx] = run; d_cur[g][idx] = run; run += d_deg_d[g][idx]; }
    }
    if (t == 0) d_rowp[g][NN] = total;
}

// 4 edges per thread
__global__ void k_fill(const int* __restrict__ s0, const int* __restrict__ d0,
                       const int* __restrict__ s1, const int* __restrict__ d1,
                       const int* __restrict__ s2, const int* __restrict__ d2) {
    int i = blockIdx.x * blockDim.x + threadIdx.x;
    const int Q = EE / 4;
    if (i >= GN * Q) return;
    int g = i / Q, e4 = (i - g * Q) * 4;
    const int* S = (g == 0) ? s0 : (g == 1) ? s1 : s2;
    const int* D = (g == 0) ? d0 : (g == 1) ? d1 : d2;
    int4 sv = *(const int4*)&S[e4];
    int4 dv = *(const int4*)&D[e4];
    int ds0 = d_deg_s[g][sv.x], ds1 = d_deg_s[g][sv.y];
    int ds2 = d_deg_s[g][sv.z], ds3 = d_deg_s[g][sv.w];
    int dd0 = d_deg_d[g][dv.x], dd1 = d_deg_d[g][dv.y];
    int dd2 = d_deg_d[g][dv.z], dd3 = d_deg_d[g][dv.w];
    int p0 = atomicAdd(&d_cur[g][dv.x], 1);
    int p1 = atomicAdd(&d_cur[g][dv.y], 1);
    int p2 = atomicAdd(&d_cur[g][dv.z], 1);
    int p3 = atomicAdd(&d_cur[g][dv.w], 1);
    int2 r0, r1, r2, r3;
    r0.x = sv.x; r0.y = __float_as_int(rsqrtf((float)max(ds0, 1) * (float)max(dd0, 1)));
    r1.x = sv.y; r1.y = __float_as_int(rsqrtf((float)max(ds1, 1) * (float)max(dd1, 1)));
    r2.x = sv.z; r2.y = __float_as_int(rsqrtf((float)max(ds2, 1) * (float)max(dd2, 1)));
    r3.x = sv.w; r3.y = __float_as_int(rsqrtf((float)max(ds3, 1) * (float)max(dd3, 1)));
    d_csr[g][p0] = r0; d_csr[g][p1] = r1; d_csr[g][p2] = r2; d_csr[g][p3] = r3;
}

__global__ void k_init(const float* __restrict__ ent) {
    int i = blockIdx.x * blockDim.x + threadIdx.x;
    if (i >= NN * KD) return;
    float v = ent[i];
    d_hh0[i] = __float2half_rn(v);
    d_sumA[i] = v;
    d_sumL[i] = 0.f;
}

// one-shot fp16 weight conversion + bias combine + W2 padding
__global__ void k_wconv(const float* __restrict__ gcnW, const float* __restrict__ gcnB,
                        const float* __restrict__ W1, const float* __restrict__ W2) {
    int i = blockIdx.x * blockDim.x + threadIdx.x;
    const int A = GN * 4 * KD * KD;          // 196608
    const int B = A + KD * H1;               // +65536
    const int C = B + H1 * H2P;              // +114688
    const int D = C + 4 * KD;                // +512
    if (i < A) {
        d_Wh[i] = __float2half_rn(gcnW[i]);
    } else if (i < B) {
        int j = i - A;
        d_W1h[j] = __float2half_rn(W1[j]);
    } else if (i < C) {
        int j = i - B;
        int k = j / H2P, n = j - k * H2P;
        d_W2h[j] = __float2half_rn(n < H2 ? W2[k * H2 + n] : 0.f);
    } else if (i < D) {
        int j = i - C;
        int l = j >> 7, col = j & 127;
        d_biasC[l][col] = gcnB[l * KD + col] + gcnB[4 * KD + l * KD + col]
                        + gcnB[8 * KD + l * KD + col];
    }
}

// ---------------- GCN aggregation (warp per (g, dst-row)), fp16 gather, MLP=8 ----
__global__ void __launch_bounds__(256) k_agg(int layer) {
    int gt = blockIdx.x * blockDim.x + threadIdx.x;
    int w = gt >> 5, lane = gt & 31;
    if (w >= GN * NN) return;
    int g = w / NN, n = w - g * NN;
    const __half* __restrict__ hin = (layer & 1) ? d_hh1 : d_hh0;
    int e0 = d_rowp[g][n], e1 = d_rowp[g][n + 1];
    const int2* __restrict__ cs = d_csr[g];
    int col = lane * 4;
    float ax = 0.f, ay = 0.f, az = 0.f, aw = 0.f;
    float bx = 0.f, by = 0.f, bz = 0.f, bw = 0.f;
    int e = e0;
    for (; e + 8 <= e1; e += 8) {
        int2 p[8];
        uint2 r[8];
#pragma unroll
        for (int q = 0; q < 8; q++) p[q] = cs[e + q];
#pragma unroll
        for (int q = 0; q < 8; q++) r[q] = *(const uint2*)(hin + p[q].x * KD + col);
#pragma unroll
        for (int q = 0; q < 8; q++) {
            float wt = __int_as_float(p[q].y);
            float2 f0 = __half22float2(*(__half2*)&r[q].x);
            float2 f1 = __half22float2(*(__half2*)&r[q].y);
            if (q & 1) { bx += wt * f0.x; by += wt * f0.y; bz += wt * f1.x; bw += wt * f1.y; }
            else       { ax += wt * f0.x; ay += wt * f0.y; az += wt * f1.x; aw += wt * f1.y; }
        }
    }
    for (; e < e1; e++) {
        int2 p = cs[e];
        uint2 r = *(const uint2*)(hin + p.x * KD + col);
        float wt = __int_as_float(p.y);
        float2 f0 = __half22float2(*(__half2*)&r.x);
        float2 f1 = __half22float2(*(__half2*)&r.y);
        ax += wt * f0.x; ay += wt * f0.y; az += wt * f1.x; aw += wt * f1.y;
    }
    __half2 h01 = __floats2half2_rn(ax + bx, ay + by);
    __half2 h23 = __floats2half2_rn(az + bz, aw + bw);
    uint2 hv;
    hv.x = *(unsigned*)&h01;
    hv.y = *(unsigned*)&h23;
    *(uint2*)&d_aggh[g][n * KD + col] = hv;
}

// ---------------- GCN GEMM (tensor cores): h_new = sum_g aggh_g @ Wh_gl + biasC
// 129 CTAs x 256 thr (8 warps). Warp = 16 rows x 128 cols. dyn smem: W (96KB) / stage (64KB).
__global__ void __launch_bounds__(256) k_gemmT(int layer) {
    extern __shared__ char smem[];
    __half* Wsm = (__half*)smem;                // 3*128*128 half = 98304 B
    float* stage = (float*)smem;                // overlay after mainloop
    int tid = threadIdx.x, w = tid >> 5, lane = tid & 31;

    {
        uint4* dst = (uint4*)Wsm;
        for (int i = tid; i < 6144; i += 256) {
            int g = i >> 11, rem = i & 2047;
            dst[i] = ((const uint4*)(d_Wh + (size_t)(g * 4 + layer) * 16384))[rem];
        }
    }
    __syncthreads();

    wmma::fragment<wmma::accumulator, 16, 16, 16, float> c[8];
#pragma unroll
    for (int n = 0; n < 8; n++) wmma::fill_fragment(c[n], 0.f);

    int row0 = blockIdx.x * 128 + w * 16;
    for (int kt = 0; kt < 24; kt++) {
        int g = kt >> 3, ks = (kt & 7) << 4;
        wmma::fragment<wmma::matrix_a, 16, 16, 16, __half, wmma::row_major> a;
        wmma::load_matrix_sync(a, d_aggh[g] + row0 * KD + ks, KD);
#pragma unroll
        for (int n = 0; n < 8; n++) {
            wmma::fragment<wmma::matrix_b, 16, 16, 16, __half, wmma::row_major> b;
            wmma::load_matrix_sync(b, Wsm + g * 16384 + ks * 128 + n * 16, 128);
            wmma::mma_sync(c[n], a, b, c[n]);
        }
    }
    __syncthreads();   // everyone done reading Wsm; reuse as stage

    float* st = stage + w * 2048;
#pragma unroll
    for (int n = 0; n < 8; n++)
        wmma::store_matrix_sync(st + n * 16, c[n], 128, wmma::mem_row_major);
    __syncwarp();

    int col0 = lane * 4;
    float4 bias = *(const float4*)&d_biasC[layer][col0];
    __half* hout = (layer & 1) ? d_hh0 : d_hh1;
    bool l2f = (layer >= 2);
#pragma unroll
    for (int r = 0; r < 16; r++) {
        float4 v = *(float4*)&st[r * 128 + col0];
        v.x += bias.x; v.y += bias.y; v.z += bias.z; v.w += bias.w;
        int base = (row0 + r) * KD + col0;
        __half2 h01 = __floats2half2_rn(v.x, v.y);
        __half2 h23 = __floats2half2_rn(v.z, v.w);
        uint2 hv;
        hv.x = *(unsigned*)&h01;
        hv.y = *(unsigned*)&h23;
        *(uint2*)&hout[base] = hv;
        float4 sa = *(float4*)&d_sumA[base];
        sa.x += v.x; sa.y += v.y; sa.z += v.z; sa.w += v.w;
        *(float4*)&d_sumA[base] = sa;
        if (l2f) {
            float4 sl = *(float4*)&d_sumL[base];
            sl.x += v.x; sl.y += v.y; sl.z += v.z; sl.w += v.w;
            *(float4*)&d_sumL[base] = sl;
        }
    }
}

// ---------------- head ----------------
__global__ void k_segstart(const int* __restrict__ seg) {
    int b = blockIdx.x * blockDim.x + threadIdx.x;
    if (b > BB) return;
    int lo = 0, hi = TT;
    while (lo < hi) { int m = (lo + hi) >> 1; if (seg[m] < b) lo = m + 1; else hi = m; }
    d_segs[b] = lo;
}

// stu[b] = mean over history of disc_full[K+hid]  (disc_full = sumL/2)
__global__ void k_stu(const int* __restrict__ hist) {
    int gt = blockIdx.x * blockDim.x + threadIdx.x;
    int w = gt >> 5, lane = gt & 31;
    if (w >= BB) return;
    int s = d_segs[w], e = d_segs[w + 1];
    const float4* __restrict__ SL = (const float4*)d_sumL;
    float4 acc = make_float4(0.f, 0.f, 0.f, 0.f);
    for (int t = s; t < e; t++) {
        int h = hist[t];
        float4 v = SL[(KD + h) * 32 + lane];
        acc.x += v.x; acc.y += v.y; acc.z += v.z; acc.w += v.w;
    }
    float inv = 0.5f / fmaxf((float)(e - s), 1.f);
    float4 o = make_float4(acc.x * inv, acc.y * inv, acc.z * inv, acc.w * inv);
    ((float4*)d_stu)[w * 32 + lane] = o;
}

// c_stu[j] = (full row j) . stuW[K:],  c_exer[j] = (full row j) . exeW[K:]   (full = sumA/5)
__global__ void k_cvec(const float* __restrict__ stuW, const float* __restrict__ exeW) {
    int tid = threadIdx.x;                  // 256 threads, 1 block
    int j = tid & 127;
    bool isE = tid >= 128;
    const float* wv = isE ? (exeW + KD) : (stuW + KD);
    float s = 0.f;
    for (int k = 0; k < KD; k++) s += d_sumA[j * KD + k] * wv[k];
    d_cvec[(isE ? KD : 0) + j] = s * 0.2f;
}

__global__ void k_x(const float* __restrict__ fsW, const float* __restrict__ fsB,
                    const float* __restrict__ feW, const float* __restrict__ feB,
                    const float* __restrict__ disc, const int* __restrict__ exid,
                    const float* __restrict__ kn) {
    int gt = blockIdx.x * blockDim.x + threadIdx.x;
    int w = gt >> 5, lane = gt & 31;
    if (w >= BB) return;
    int eid = exid[w];
    float4 sv = ((const float4*)d_stu)[w * 32 + lane];
    float4 ev = ((const float4*)d_sumA)[(KD + eid) * 32 + lane];
    float4 wa = ((const float4*)fsW)[lane];
    float4 wb = ((const float4*)feW)[lane];
    float ps = sv.x * wa.x + sv.y * wa.y + sv.z * wa.z + sv.w * wa.w;
    float pe = (ev.x * wb.x + ev.y * wb.y + ev.z * wb.z + ev.w * wb.w) * 0.2f;
#pragma unroll
    for (int o = 16; o; o >>= 1) {
        ps += __shfl_xor_sync(0xffffffffu, ps, o);
        pe += __shfl_xor_sync(0xffffffffu, pe, o);
    }
    float ed = 10.f * sigm(disc[eid]);
    float4 cs = ((const float4*)d_cvec)[lane];
    float4 ce = ((const float4*)(d_cvec + KD))[lane];
    float4 kv = ((const float4*)kn)[w * 32 + lane];
    float bs = fsB[0], be = feB[0];
    float x0 = ed * (sigm(ps + cs.x + bs) - sigm(pe + ce.x + be)) * kv.x;
    float x1 = ed * (sigm(ps + cs.y + bs) - sigm(pe + ce.y + be)) * kv.y;
    float x2 = ed * (sigm(ps + cs.z + bs) - sigm(pe + ce.z + be)) * kv.z;
    float x3 = ed * (sigm(ps + cs.w + bs) - sigm(pe + ce.w + be)) * kv.w;
    __half2 h01 = __floats2half2_rn(x0, x1);
    __half2 h23 = __floats2half2_rn(x2, x3);
    uint2 hv;
    hv.x = *(unsigned*)&h01;
    hv.y = *(unsigned*)&h23;
    *(uint2*)&d_xh[w * KD + lane * 4] = hv;
}

// MLP layer 1 (tensor): x(4096x128) @ W1(128x512) -> sigmoid -> d_x1h (fp16)
// grid (32,4), 256 thr. Warp = 16 rows x 128 cols. dyn smem 64KB (Bsm 32KB / stage 64KB).
__global__ void __launch_bounds__(256) k_mlp1T(const float* __restrict__ b1) {
    extern __shared__ char smem[];
    __half* Bsm = (__half*)smem;
    float* stage = (float*)smem;
    int tid = threadIdx.x, w = tid >> 5, lane = tid & 31;
    int n0 = blockIdx.y * 128;

    for (int i = tid; i < 2048; i += 256) {
        int k = i >> 4, nq = (i & 15) << 3;
        *(uint4*)&Bsm[k * 128 + nq] = *(const uint4*)&d_W1h[k * H1 + n0 + nq];
    }
    __syncthreads();

    wmma::fragment<wmma::accumulator, 16, 16, 16, float> c[8];
#pragma unroll
    for (int n = 0; n < 8; n++) wmma::fill_fragment(c[n], 0.f);

    int row0 = blockIdx.x * 128 + w * 16;
    for (int kt = 0; kt < 8; kt++) {
        wmma::fragment<wmma::matrix_a, 16, 16, 16, __half, wmma::row_major> a;
        wmma::load_matrix_sync(a, d_xh + row0 * KD + kt * 16, KD);
#pragma unroll
        for (int n = 0; n < 8; n++) {
            wmma::fragment<wmma::matrix_b, 16, 16, 16, __half, wmma::row_major> b;
            wmma::load_matrix_sync(b, Bsm + kt * 16 * 128 + n * 16, 128);
            wmma::mma_sync(c[n], a, b, c[n]);
        }
    }
    __syncthreads();

    float* st = stage + w * 2048;
#pragma unroll
    for (int n = 0; n < 8; n++)
        wmma::store_matrix_sync(st + n * 16, c[n], 128, wmma::mem_row_major);
    __syncwarp();

    int col0 = lane * 4;
    float4 bias = *(const float4*)&b1[n0 + col0];
#pragma unroll
    for (int r = 0; r < 16; r++) {
        float4 v = *(float4*)&st[r * 128 + col0];
        float y0 = sigm(v.x + bias.x);
        float y1 = sigm(v.y + bias.y);
        float y2 = sigm(v.z + bias.z);
        float y3 = sigm(v.w + bias.w);
        __half2 h01 = __floats2half2_rn(y0, y1);
        __half2 h23 = __floats2half2_rn(y2, y3);
        uint2 hv;
        hv.x = *(unsigned*)&h01;
        hv.y = *(unsigned*)&h23;
        *(uint2*)&d_x1h[(row0 + r) * H1 + n0 + col0] = hv;
    }
}

// MLP layer 2 (tensor): x1(4096x512) @ W2pad(512x224) -> sigmoid -> d_x2 (fp32, 216 cols)
// grid 32, 256 thr. Warp = 16 rows x 224 cols (14 frags). B read from global (L2-served).
__global__ void __launch_bounds__(256) k_mlp2T(const float* __restrict__ b2) {
    extern __shared__ float stage[];    // 8 * 16 * 224 floats = 114688 B
    int tid = threadIdx.x, w = tid >> 5, lane = tid & 31;

    wmma::fragment<wmma::accumulator, 16, 16, 16, float> c[14];
#pragma unroll
    for (int n = 0; n < 14; n++) wmma::fill_fragment(c[n], 0.f);

    int row0 = blockIdx.x * 128 + w * 16;
    for (int kt = 0; kt < 32; kt++) {
        wmma::fragment<wmma::matrix_a, 16, 16, 16, __half, wmma::row_major> a;
        wmma::load_matrix_sync(a, d_x1h + row0 * H1 + kt * 16, H1);
#pragma unroll
        for (int n = 0; n < 14; n++) {
            wmma::fragment<wmma::matrix_b, 16, 16, 16, __half, wmma::row_major> b;
            wmma::load_matrix_sync(b, d_W2h + kt * 16 * H2P + n * 16, H2P);
            wmma::mma_sync(c[n], a, b, c[n]);
        }
    }
    float* st = stage + w * (16 * H2P);
#pragma unroll
    for (int n = 0; n < 14; n++)
        wmma::store_matrix_sync(st + n * 16, c[n], H2P, wmma::mem_row_major);
    __syncwarp();

#pragma unroll
    for (int j = 0; j < 7; j++) {
        int col = lane * 7 + j;
        if (col < H2) {
            float bb = b2[col];
#pragma unroll
            for (int r = 0; r < 16; r++) {
                float v = st[r * H2P + col];
                d_x2[(row0 + r) * H2 + col] = sigm(v + bb);
            }
        }
    }
}

__global__ void k_out(const float* __restrict__ W3, const float* __restrict__ b3,
                      float* __restrict__ out) {
    int gt = blockIdx.x * blockDim.x + threadIdx.x;
    int w = gt >> 5, lane = gt & 31;
    if (w >= BB) return;
    float s = 0.f;
    for (int k = lane; k < H2; k += 32) s += d_x2[w * H2 + k] * W3[k];
#pragma unroll
    for (int o = 16; o; o >>= 1) s += __shfl_xor_sync(0xffffffffu, s, o);
    if (lane == 0) out[w] = sigm(s + b3[0]);
}

// ---------------- launch ----------------
extern "C" void kernel_launch(void* const* d_in, const int* in_sizes, int n_in,
                              void* d_out, int out_size) {
    const float* ent  = (const float*)d_in[0];
    const float* gcnW = (const float*)d_in[1];
    const float* gcnB = (const float*)d_in[2];
    const float* fsW  = (const float*)d_in[3];
    const float* fsB  = (const float*)d_in[4];
    const float* feW  = (const float*)d_in[5];
    const float* feB  = (const float*)d_in[6];
    const float* disc = (const float*)d_in[7];
    const float* W1   = (const float*)d_in[8];
    const float* b1   = (const float*)d_in[9];
    const float* W2   = (const float*)d_in[10];
    const float* b2   = (const float*)d_in[11];
    const float* W3   = (const float*)d_in[12];
    const float* b3   = (const float*)d_in[13];
    const int* ss = (const int*)d_in[14];
    const int* sd = (const int*)d_in[15];
    const int* ps = (const int*)d_in[16];
    const int* pd = (const int*)d_in[17];
    const int* es = (const int*)d_in[18];
    const int* ed = (const int*)d_in[19];
    const int* exid = (const int*)d_in[21];
    const float* kn  = (const float*)d_in[22];
    const int* hid   = (const int*)d_in[23];
    const int* hseg  = (const int*)d_in[24];
    float* out = (float*)d_out;

    cudaFuncSetAttribute(k_gemmT, cudaFuncAttributeMaxDynamicSharedMemorySize, 98304);
    cudaFuncSetAttribute(k_mlp1T, cudaFuncAttributeMaxDynamicSharedMemorySize, 65536);
    cudaFuncSetAttribute(k_mlp2T, cudaFuncAttributeMaxDynamicSharedMemorySize, 114688);

    k_zero_deg<<<(GN * NN + 255) / 256, 256>>>();
    k_degree<<<(GN * (EE / 4) + 255) / 256, 256>>>(ss, sd, ps, pd, es, ed);
    k_scan<<<GN, 512>>>();
    k_fill<<<(GN * (EE / 4) + 255) / 256, 256>>>(ss, sd, ps, pd, es, ed);
    k_init<<<(NN * KD + 255) / 256, 256>>>(ent);
    k_wconv<<<(GN * 4 * KD * KD + KD * H1 + H1 * H2P + 4 * KD + 255) / 256, 256>>>(
        gcnW, gcnB, W1, W2);

    for (int l = 0; l < 4; l++) {
        k_agg<<<(GN * NN * 32 + 255) / 256, 256>>>(l);
        k_gemmT<<<NN / 128, 256, 98304>>>(l);
    }

    k_segstart<<<(BB + 1 + 255) / 256, 256>>>(hseg);
    k_stu<<<(BB * 32 + 255) / 256, 256>>>(hid);
    k_cvec<<<1, 256>>>(fsW, feW);
    k_x<<<(BB * 32 + 255) / 256, 256>>>(fsW, fsB, feW, feB, disc, exid, kn);

    dim3 g1(BB / 128, H1 / 128);
    k_mlp1T<<<g1, 256, 65536>>>(b1);
    k_mlp2T<<<BB / 128, 256, 114688>>>(b2);
    k_out<<<(BB * 32 + 255) / 256, 256>>>(W3, b3, out);
}

// round 5
// speedup vs baseline: 1.6306x; 1.0887x over previous
#include <cuda_runtime.h>
#include <cuda_fp16.h>
#include <mma.h>

using namespace nvcuda;

#define GN 3
constexpr int NN = 16512;     // K + EXER entities  (= 129 * 128 exactly)
constexpr int KD = 128;       // embedding dim
constexpr int EE = 400000;    // edges per graph (divisible by 8)
constexpr int BB = 4096;      // batch
constexpr int TT = 204800;    // history length
constexpr int H1 = 512;
constexpr int H2 = 216;
constexpr int H2P = 224;      // padded to 14*16

// ---------------- scratch (static device globals; no allocation) ----------------
__device__ int      d_deg_s[GN][NN];
__device__ int      d_deg_d[GN][NN];
__device__ int      d_rowp[GN][NN + 1];
__device__ int      d_cur[GN][NN];
__device__ unsigned d_csr[GN][EE];   // low16 = src idx, high16 = fp16 norm weight
__device__ __half   d_hh0[NN * KD];  // fp16 activations (gather source)
__device__ __half   d_hh1[NN * KD];
__device__ __half   d_aggh[GN][NN * KD];   // fp16 aggregation output (A for tensor GEMM)
__device__ __half   d_Wh[GN * 4 * KD * KD];// fp16 GCN weights [g][l][k][n]
__device__ float    d_biasC[4][KD];        // per-layer combined bias (sum over g)
__device__ __half   d_W1h[KD * H1];
__device__ __half   d_W2h[H1 * H2P];       // zero-padded cols
__device__ float    d_sumA[NN * KD];  // entity_emb + h1+h2+h3+h4  (full = /5)
__device__ float    d_sumL[NN * KD];  // h3 (partial; finalized into fp16 below)
__device__ __half   d_sumLh[NN * KD]; // h3 + h4 in fp16 (disc_full*2) for k_stu gather
__device__ float    d_stu[BB * KD];
__device__ int      d_segs[BB + 1];
__device__ float    d_cvec[2 * KD];
__device__ __half   d_xh[BB * KD];
__device__ __half   d_x1h[BB * H1];
__device__ float    d_x2[BB * H2];

__device__ __forceinline__ float sigm(float x) { return 1.f / (1.f + __expf(-x)); }

// ---------------- CSR build ----------------
__global__ void k_zero_deg() {
    int i = blockIdx.x * blockDim.x + threadIdx.x;
    if (i < GN * NN) { ((int*)d_deg_s)[i] = 0; ((int*)d_deg_d)[i] = 0; }
}

// 8 edges per thread -> MLP=8 on the L2 atomics
__global__ void k_degree(const int* __restrict__ s0, const int* __restrict__ d0,
                         const int* __restrict__ s1, const int* __restrict__ d1,
                         const int* __restrict__ s2, const int* __restrict__ d2) {
    int i = blockIdx.x * blockDim.x + threadIdx.x;
    const int Q = EE / 8;
    if (i >= GN * Q) return;
    int g = i / Q, e8 = (i - g * Q) * 8;
    const int* S = (g == 0) ? s0 : (g == 1) ? s1 : s2;
    const int* D = (g == 0) ? d0 : (g == 1) ? d1 : d2;
    int4 sa = *(const int4*)&S[e8];
    int4 sb = *(const int4*)&S[e8 + 4];
    int4 da = *(const int4*)&D[e8];
    int4 db = *(const int4*)&D[e8 + 4];
    atomicAdd(&d_deg_s[g][sa.x], 1); atomicAdd(&d_deg_s[g][sa.y], 1);
    atomicAdd(&d_deg_s[g][sa.z], 1); atomicAdd(&d_deg_s[g][sa.w], 1);
    atomicAdd(&d_deg_s[g][sb.x], 1); atomicAdd(&d_deg_s[g][sb.y], 1);
    atomicAdd(&d_deg_s[g][sb.z], 1); atomicAdd(&d_deg_s[g][sb.w], 1);
    atomicAdd(&d_deg_d[g][da.x], 1); atomicAdd(&d_deg_d[g][da.y], 1);
    atomicAdd(&d_deg_d[g][da.z], 1); atomicAdd(&d_deg_d[g][da.w], 1);
    atomicAdd(&d_deg_d[g][db.x], 1); atomicAdd(&d_deg_d[g][db.y], 1);
    atomicAdd(&d_deg_d[g][db.z], 1); atomicAdd(&d_deg_d[g][db.w], 1);
}

// exclusive scan of in-degree -> row_ptr (+cursor copy). one block per graph, 1024 thr.
__global__ void k_scan() {
    __shared__ int sA[1024], sB[1024];
    int g = blockIdx.x, t = threadIdx.x;
    const int CH = (NN + 1023) / 1024;   // 17
    int base = t * CH;
    int s = 0;
    for (int i = 0; i < CH; i++) { int idx = base + i; if (idx < NN) s += d_deg_d[g][idx]; }
    sA[t] = s;
    __syncthreads();
    int* a = sA; int* b = sB;
    for (int off = 1; off < 1024; off <<= 1) {
        b[t] = a[t] + ((t >= off) ? a[t - off] : 0);
        __syncthreads();
        int* tmp = a; a = b; b = tmp;
    }
    int incl = a[t];
    int total = a[1023];
    int run = incl - s;
    for (int i = 0; i < CH; i++) {
        int idx = base + i;
        if (idx < NN) { d_rowp[g][idx] = run; d_cur[g][idx] = run; run += d_deg_d[g][idx]; }
    }
    if (t == 0) d_rowp[g][NN] = total;
}

__device__ __forceinline__ unsigned mk_rec(int src, int degs, int degd) {
    float w = rsqrtf((float)max(degs, 1) * (float)max(degd, 1));
    unsigned hb = (unsigned)__half_as_ushort(__float2half_rn(w));
    return (unsigned)src | (hb << 16);
}

// 8 edges per thread, packed 4-byte records
__global__ void k_fill(const int* __restrict__ s0, const int* __restrict__ d0,
                       const int* __restrict__ s1, const int* __restrict__ d1,
                       const int* __restrict__ s2, const int* __restrict__ d2) {
    int i = blockIdx.x * blockDim.x + threadIdx.x;
    const int Q = EE / 8;
    if (i >= GN * Q) return;
    int g = i / Q, e8 = (i - g * Q) * 8;
    const int* S = (g == 0) ? s0 : (g == 1) ? s1 : s2;
    const int* D = (g == 0) ? d0 : (g == 1) ? d1 : d2;
    int sv[8], dv[8];
    *(int4*)&sv[0] = *(const int4*)&S[e8];
    *(int4*)&sv[4] = *(const int4*)&S[e8 + 4];
    *(int4*)&dv[0] = *(const int4*)&D[e8];
    *(int4*)&dv[4] = *(const int4*)&D[e8 + 4];
    int ds[8], dd[8];
#pragma unroll
    for (int q = 0; q < 8; q++) ds[q] = d_deg_s[g][sv[q]];
#pragma unroll
    for (int q = 0; q < 8; q++) dd[q] = d_deg_d[g][dv[q]];
    int pos[8];
#pragma unroll
    for (int q = 0; q < 8; q++) pos[q] = atomicAdd(&d_cur[g][dv[q]], 1);
#pragma unroll
    for (int q = 0; q < 8; q++) d_csr[g][pos[q]] = mk_rec(sv[q], ds[q], dd[q]);
}

__global__ void k_init(const float* __restrict__ ent) {
    int i = blockIdx.x * blockDim.x + threadIdx.x;
    if (i >= NN * KD) return;
    float v = ent[i];
    d_hh0[i] = __float2half_rn(v);
    d_sumA[i] = v;
    d_sumL[i] = 0.f;
}

// one-shot fp16 weight conversion + bias combine + W2 padding
__global__ void k_wconv(const float* __restrict__ gcnW, const float* __restrict__ gcnB,
                        const float* __restrict__ W1, const float* __restrict__ W2) {
    int i = blockIdx.x * blockDim.x + threadIdx.x;
    const int A = GN * 4 * KD * KD;          // 196608
    const int B = A + KD * H1;               // +65536
    const int C = B + H1 * H2P;              // +114688
    const int D = C + 4 * KD;                // +512
    if (i < A) {
        d_Wh[i] = __float2half_rn(gcnW[i]);
    } else if (i < B) {
        int j = i - A;
        d_W1h[j] = __float2half_rn(W1[j]);
    } else if (i < C) {
        int j = i - B;
        int k = j / H2P, n = j - k * H2P;
        d_W2h[j] = __float2half_rn(n < H2 ? W2[k * H2 + n] : 0.f);
    } else if (i < D) {
        int j = i - C;
        int l = j >> 7, col = j & 127;
        d_biasC[l][col] = gcnB[l * KD + col] + gcnB[4 * KD + l * KD + col]
                        + gcnB[8 * KD + l * KD + col];
    }
}

// ---------------- GCN aggregation: warp per (g, dst-row), 2 edges per LDG.128 ----
// lanes 0-15 process even edges, lanes 16-31 odd. Each lane covers 8 columns.
__global__ void __launch_bounds__(256) k_agg(int layer) {
    int gt = blockIdx.x * blockDim.x + threadIdx.x;
    int w = gt >> 5, lane = gt & 31;
    if (w >= GN * NN) return;
    int g = w / NN, n = w - g * NN;
    const __half* __restrict__ hin = (layer & 1) ? d_hh1 : d_hh0;
    int e0 = d_rowp[g][n], e1 = d_rowp[g][n + 1];
    const unsigned* __restrict__ cs = d_csr[g];
    int half = lane >> 4, hl = lane & 15;
    int colb = hl * 8;
    float acc[8];
#pragma unroll
    for (int j = 0; j < 8; j++) acc[j] = 0.f;

    int ee = e0 + half;
    // 4 pairs (8 edges) per iteration -> 4 gathers in flight per lane
    for (; ee + 6 < e1; ee += 8) {
        unsigned r0 = cs[ee], r1 = cs[ee + 2], r2 = cs[ee + 4], r3 = cs[ee + 6];
        uint4 v0 = *(const uint4*)(hin + (r0 & 0xFFFFu) * KD + colb);
        uint4 v1 = *(const uint4*)(hin + (r1 & 0xFFFFu) * KD + colb);
        uint4 v2 = *(const uint4*)(hin + (r2 & 0xFFFFu) * KD + colb);
        uint4 v3 = *(const uint4*)(hin + (r3 & 0xFFFFu) * KD + colb);
        float w0 = __half2float(__ushort_as_half((unsigned short)(r0 >> 16)));
        float w1 = __half2float(__ushort_as_half((unsigned short)(r1 >> 16)));
        float w2 = __half2float(__ushort_as_half((unsigned short)(r2 >> 16)));
        float w3 = __half2float(__ushort_as_half((unsigned short)(r3 >> 16)));
        const unsigned* vv;
        float2 f;
        vv = &v0.x;
#pragma unroll
        for (int q = 0; q < 4; q++) {
            f = __half22float2(*(const __half2*)&vv[q]);
            acc[2 * q] += w0 * f.x; acc[2 * q + 1] += w0 * f.y;
        }
        vv = &v1.x;
#pragma unroll
        for (int q = 0; q < 4; q++) {
            f = __half22float2(*(const __half2*)&vv[q]);
            acc[2 * q] += w1 * f.x; acc[2 * q + 1] += w1 * f.y;
        }
        vv = &v2.x;
#pragma unroll
        for (int q = 0; q < 4; q++) {
            f = __half22float2(*(const __half2*)&vv[q]);
            acc[2 * q] += w2 * f.x; acc[2 * q + 1] += w2 * f.y;
        }
        vv = &v3.x;
#pragma unroll
        for (int q = 0; q < 4; q++) {
            f = __half22float2(*(const __half2*)&vv[q]);
            acc[2 * q] += w3 * f.x; acc[2 * q + 1] += w3 * f.y;
        }
    }
    for (; ee < e1; ee += 2) {
        unsigned r = cs[ee];
        uint4 v = *(const uint4*)(hin + (r & 0xFFFFu) * KD + colb);
        float wt = __half2float(__ushort_as_half((unsigned short)(r >> 16)));
        const unsigned* vv = &v.x;
#pragma unroll
        for (int q = 0; q < 4; q++) {
            float2 f = __half22float2(*(const __half2*)&vv[q]);
            acc[2 * q] += wt * f.x; acc[2 * q + 1] += wt * f.y;
        }
    }
    // combine even/odd halves: lane i <-> lane i+16 hold same columns
#pragma unroll
    for (int j = 0; j < 8; j++)
        acc[j] += __shfl_xor_sync(0xffffffffu, acc[j], 16);
    if (half == 0) {
        uint4 hv;
        __half2 h;
        h = __floats2half2_rn(acc[0], acc[1]); hv.x = *(unsigned*)&h;
        h = __floats2half2_rn(acc[2], acc[3]); hv.y = *(unsigned*)&h;
        h = __floats2half2_rn(acc[4], acc[5]); hv.z = *(unsigned*)&h;
        h = __floats2half2_rn(acc[6], acc[7]); hv.w = *(unsigned*)&h;
        *(uint4*)&d_aggh[g][n * KD + colb] = hv;
    }
}

// ---------------- GCN GEMM (tensor cores): h_new = sum_g aggh_g @ Wh_gl + biasC
__global__ void __launch_bounds__(256) k_gemmT(int layer) {
    extern __shared__ char smem[];
    __half* Wsm = (__half*)smem;                // 3*128*128 half = 98304 B
    float* stage = (float*)smem;                // overlay after mainloop
    int tid = threadIdx.x, w = tid >> 5, lane = tid & 31;

    {
        uint4* dst = (uint4*)Wsm;
        for (int i = tid; i < 6144; i += 256) {
            int g = i >> 11, rem = i & 2047;
            dst[i] = ((const uint4*)(d_Wh + (size_t)(g * 4 + layer) * 16384))[rem];
        }
    }
    __syncthreads();

    wmma::fragment<wmma::accumulator, 16, 16, 16, float> c[8];
#pragma unroll
    for (int n = 0; n < 8; n++) wmma::fill_fragment(c[n], 0.f);

    int row0 = blockIdx.x * 128 + w * 16;
    for (int kt = 0; kt < 24; kt++) {
        int g = kt >> 3, ks = (kt & 7) << 4;
        wmma::fragment<wmma::matrix_a, 16, 16, 16, __half, wmma::row_major> a;
        wmma::load_matrix_sync(a, d_aggh[g] + row0 * KD + ks, KD);
#pragma unroll
        for (int n = 0; n < 8; n++) {
            wmma::fragment<wmma::matrix_b, 16, 16, 16, __half, wmma::row_major> b;
            wmma::load_matrix_sync(b, Wsm + g * 16384 + ks * 128 + n * 16, 128);
            wmma::mma_sync(c[n], a, b, c[n]);
        }
    }
    __syncthreads();   // everyone done reading Wsm; reuse as stage

    float* st = stage + w * 2048;
#pragma unroll
    for (int n = 0; n < 8; n++)
        wmma::store_matrix_sync(st + n * 16, c[n], 128, wmma::mem_row_major);
    __syncwarp();

    int col0 = lane * 4;
    float4 bias = *(const float4*)&d_biasC[layer][col0];
    __half* hout = (layer & 1) ? d_hh0 : d_hh1;
#pragma unroll
    for (int r = 0; r < 16; r++) {
        float4 v = *(float4*)&st[r * 128 + col0];
        v.x += bias.x; v.y += bias.y; v.z += bias.z; v.w += bias.w;
        int base = (row0 + r) * KD + col0;
        __half2 h01 = __floats2half2_rn(v.x, v.y);
        __half2 h23 = __floats2half2_rn(v.z, v.w);
        uint2 hv;
        hv.x = *(unsigned*)&h01;
        hv.y = *(unsigned*)&h23;
        *(uint2*)&hout[base] = hv;
        float4 sa = *(float4*)&d_sumA[base];
        sa.x += v.x; sa.y += v.y; sa.z += v.z; sa.w += v.w;
        *(float4*)&d_sumA[base] = sa;
        if (layer == 2) {
            *(float4*)&d_sumL[base] = v;       // h3
        } else if (layer == 3) {
            float4 sl = *(float4*)&d_sumL[base];
            __half2 s01 = __floats2half2_rn(sl.x + v.x, sl.y + v.y);
            __half2 s23 = __floats2half2_rn(sl.z + v.z, sl.w + v.w);
            uint2 sv2;
            sv2.x = *(unsigned*)&s01;
            sv2.y = *(unsigned*)&s23;
            *(uint2*)&d_sumLh[base] = sv2;     // h3+h4 fp16
        }
    }
}

// ---------------- head ----------------
__global__ void k_segstart(const int* __restrict__ seg) {
    int b = blockIdx.x * blockDim.x + threadIdx.x;
    if (b > BB) return;
    int lo = 0, hi = TT;
    while (lo < hi) { int m = (lo + hi) >> 1; if (seg[m] < b) lo = m + 1; else hi = m; }
    d_segs[b] = lo;
}

// stu[b] = mean over history of disc_full[K+hid] ; sumLh fp16 gather (8 B/lane)
__global__ void k_stu(const int* __restrict__ hist) {
    int gt = blockIdx.x * blockDim.x + threadIdx.x;
    int w = gt >> 5, lane = gt & 31;
    if (w >= BB) return;
    int s = d_segs[w], e = d_segs[w + 1];
    const __half* __restrict__ SL = d_sumLh;
    int col = lane * 4;
    float ax = 0.f, ay = 0.f, az = 0.f, aw = 0.f;
    int t = s;
    for (; t + 4 <= e; t += 4) {
        int4 h4 = make_int4(hist[t], hist[t + 1], hist[t + 2], hist[t + 3]);
        uint2 r0 = *(const uint2*)(SL + (KD + h4.x) * KD + col);
        uint2 r1 = *(const uint2*)(SL + (KD + h4.y) * KD + col);
        uint2 r2 = *(const uint2*)(SL + (KD + h4.z) * KD + col);
        uint2 r3 = *(const uint2*)(SL + (KD + h4.w) * KD + col);
        float2 f;
        f = __half22float2(*(__half2*)&r0.x); ax += f.x; ay += f.y;
        f = __half22float2(*(__half2*)&r0.y); az += f.x; aw += f.y;
        f = __half22float2(*(__half2*)&r1.x); ax += f.x; ay += f.y;
        f = __half22float2(*(__half2*)&r1.y); az += f.x; aw += f.y;
        f = __half22float2(*(__half2*)&r2.x); ax += f.x; ay += f.y;
        f = __half22float2(*(__half2*)&r2.y); az += f.x; aw += f.y;
        f = __half22float2(*(__half2*)&r3.x); ax += f.x; ay += f.y;
        f = __half22float2(*(__half2*)&r3.y); az += f.x; aw += f.y;
    }
    for (; t < e; t++) {
        int h = hist[t];
        uint2 r = *(const uint2*)(SL + (KD + h) * KD + col);
        float2 f;
        f = __half22float2(*(__half2*)&r.x); ax += f.x; ay += f.y;
        f = __half22float2(*(__half2*)&r.y); az += f.x; aw += f.y;
    }
    float inv = 0.5f / fmaxf((float)(e - s), 1.f);
    float4 o = make_float4(ax * inv, ay * inv, az * inv, aw * inv);
    *(float4*)&d_stu[w * KD + col] = o;
}

// c_stu[j] = (full row j) . stuW[K:],  c_exer[j] = (full row j) . exeW[K:]   (full = sumA/5)
__global__ void k_cvec(const float* __restrict__ stuW, const float* __restrict__ exeW) {
    int tid = threadIdx.x;                  // 256 threads, 1 block
    int j = tid & 127;
    bool isE = tid >= 128;
    const float* wv = isE ? (exeW + KD) : (stuW + KD);
    float s = 0.f;
    for (int k = 0; k < KD; k++) s += d_sumA[j * KD + k] * wv[k];
    d_cvec[(isE ? KD : 0) + j] = s * 0.2f;
}

__global__ void k_x(const float* __restrict__ fsW, const float* __restrict__ fsB,
                    const float* __restrict__ feW, const float* __restrict__ feB,
                    const float* __restrict__ disc, const int* __restrict__ exid,
                    const float* __restrict__ kn) {
    int gt = blockIdx.x * blockDim.x + threadIdx.x;
    int w = gt >> 5, lane = gt & 31;
    if (w >= BB) return;
    int eid = exid[w];
    float4 sv = ((const float4*)d_stu)[w * 32 + lane];
    float4 ev = ((const float4*)d_sumA)[(KD + eid) * 32 + lane];
    float4 wa = ((const float4*)fsW)[lane];
    float4 wb = ((const float4*)feW)[lane];
    float ps = sv.x * wa.x + sv.y * wa.y + sv.z * wa.z + sv.w * wa.w;
    float pe = (ev.x * wb.x + ev.y * wb.y + ev.z * wb.z + ev.w * wb.w) * 0.2f;
#pragma unroll
    for (int o = 16; o; o >>= 1) {
        ps += __shfl_xor_sync(0xffffffffu, ps, o);
        pe += __shfl_xor_sync(0xffffffffu, pe, o);
    }
    float ed = 10.f * sigm(disc[eid]);
    float4 cs = ((const float4*)d_cvec)[lane];
    float4 ce = ((const float4*)(d_cvec + KD))[lane];
    float4 kv = ((const float4*)kn)[w * 32 + lane];
    float bs = fsB[0], be = feB[0];
    float x0 = ed * (sigm(ps + cs.x + bs) - sigm(pe + ce.x + be)) * kv.x;
    float x1 = ed * (sigm(ps + cs.y + bs) - sigm(pe + ce.y + be)) * kv.y;
    float x2 = ed * (sigm(ps + cs.z + bs) - sigm(pe + ce.z + be)) * kv.z;
    float x3 = ed * (sigm(ps + cs.w + bs) - sigm(pe + ce.w + be)) * kv.w;
    __half2 h01 = __floats2half2_rn(x0, x1);
    __half2 h23 = __floats2half2_rn(x2, x3);
    uint2 hv;
    hv.x = *(unsigned*)&h01;
    hv.y = *(unsigned*)&h23;
    *(uint2*)&d_xh[w * KD + lane * 4] = hv;
}

// MLP layer 1 (tensor): x(4096x128) @ W1(128x512) -> sigmoid -> d_x1h (fp16)
__global__ void __launch_bounds__(256) k_mlp1T(const float* __restrict__ b1) {
    extern __shared__ char smem[];
    __half* Bsm = (__half*)smem;
    float* stage = (float*)smem;
    int tid = threadIdx.x, w = tid >> 5, lane = tid & 31;
    int n0 = blockIdx.y * 128;

    for (int i = tid; i < 2048; i += 256) {
        int k = i >> 4, nq = (i & 15) << 3;
        *(uint4*)&Bsm[k * 128 + nq] = *(const uint4*)&d_W1h[k * H1 + n0 + nq];
    }
    __syncthreads();

    wmma::fragment<wmma::accumulator, 16, 16, 16, float> c[8];
#pragma unroll
    for (int n = 0; n < 8; n++) wmma::fill_fragment(c[n], 0.f);

    int row0 = blockIdx.x * 128 + w * 16;
    for (int kt = 0; kt < 8; kt++) {
        wmma::fragment<wmma::matrix_a, 16, 16, 16, __half, wmma::row_major> a;
        wmma::load_matrix_sync(a, d_xh + row0 * KD + kt * 16, KD);
#pragma unroll
        for (int n = 0; n < 8; n++) {
            wmma::fragment<wmma::matrix_b, 16, 16, 16, __half, wmma::row_major> b;
            wmma::load_matrix_sync(b, Bsm + kt * 16 * 128 + n * 16, 128);
            wmma::mma_sync(c[n], a, b, c[n]);
        }
    }
    __syncthreads();

    float* st = stage + w * 2048;
#pragma unroll
    for (int n = 0; n < 8; n++)
        wmma::store_matrix_sync(st + n * 16, c[n], 128, wmma::mem_row_major);
    __syncwarp();

    int col0 = lane * 4;
    float4 bias = *(const float4*)&b1[n0 + col0];
#pragma unroll
    for (int r = 0; r < 16; r++) {
        float4 v = *(float4*)&st[r * 128 + col0];
        float y0 = sigm(v.x + bias.x);
        float y1 = sigm(v.y + bias.y);
        float y2 = sigm(v.z + bias.z);
        float y3 = sigm(v.w + bias.w);
        __half2 h01 = __floats2half2_rn(y0, y1);
        __half2 h23 = __floats2half2_rn(y2, y3);
        uint2 hv;
        hv.x = *(unsigned*)&h01;
        hv.y = *(unsigned*)&h23;
        *(uint2*)&d_x1h[(row0 + r) * H1 + n0 + col0] = hv;
    }
}

// MLP layer 2 (tensor): x1(4096x512) @ W2pad(512x224) -> sigmoid -> d_x2 (fp32, 216 cols)
__global__ void __launch_bounds__(256) k_mlp2T(const float* __restrict__ b2) {
    extern __shared__ float stage[];    // 8 * 16 * 224 floats = 114688 B
    int tid = threadIdx.x, w = tid >> 5, lane = tid & 31;

    wmma::fragment<wmma::accumulator, 16, 16, 16, float> c[14];
#pragma unroll
    for (int n = 0; n < 14; n++) wmma::fill_fragment(c[n], 0.f);

    int row0 = blockIdx.x * 128 + w * 16;
    for (int kt = 0; kt < 32; kt++) {
        wmma::fragment<wmma::matrix_a, 16, 16, 16, __half, wmma::row_major> a;
        wmma::load_matrix_sync(a, d_x1h + row0 * H1 + kt * 16, H1);
#pragma unroll
        for (int n = 0; n < 14; n++) {
            wmma::fragment<wmma::matrix_b, 16, 16, 16, __half, wmma::row_major> b;
            wmma::load_matrix_sync(b, d_W2h + kt * 16 * H2P + n * 16, H2P);
            wmma::mma_sync(c[n], a, b, c[n]);
        }
    }
    float* st = stage + w * (16 * H2P);
#pragma unroll
    for (int n = 0; n < 14; n++)
        wmma::store_matrix_sync(st + n * 16, c[n], H2P, wmma::mem_row_major);
    __syncwarp();

#pragma unroll
    for (int j = 0; j < 7; j++) {
        int col = lane * 7 + j;
        if (col < H2) {
            float bb = b2[col];
#pragma unroll
            for (int r = 0; r < 16; r++) {
                float v = st[r * H2P + col];
                d_x2[(row0 + r) * H2 + col] = sigm(v + bb);
            }
        }
    }
}

__global__ void k_out(const float* __restrict__ W3, const float* __restrict__ b3,
                      float* __restrict__ out) {
    int gt = blockIdx.x * blockDim.x + threadIdx.x;
    int w = gt >> 5, lane = gt & 31;
    if (w >= BB) return;
    float s = 0.f;
    for (int k = lane; k < H2; k += 32) s += d_x2[w * H2 + k] * W3[k];
#pragma unroll
    for (int o = 16; o; o >>= 1) s += __shfl_xor_sync(0xffffffffu, s, o);
    if (lane == 0) out[w] = sigm(s + b3[0]);
}

// ---------------- launch ----------------
extern "C" void kernel_launch(void* const* d_in, const int* in_sizes, int n_in,
                              void* d_out, int out_size) {
    const float* ent  = (const float*)d_in[0];
    const float* gcnW = (const float*)d_in[1];
    const float* gcnB = (const float*)d_in[2];
    const float* fsW  = (const float*)d_in[3];
    const float* fsB  = (const float*)d_in[4];
    const float* feW  = (const float*)d_in[5];
    const float* feB  = (const float*)d_in[6];
    const float* disc = (const float*)d_in[7];
    const float* W1   = (const float*)d_in[8];
    const float* b1   = (const float*)d_in[9];
    const float* W2   = (const float*)d_in[10];
    const float* b2   = (const float*)d_in[11];
    const float* W3   = (const float*)d_in[12];
    const float* b3   = (const float*)d_in[13];
    const int* ss = (const int*)d_in[14];
    const int* sd = (const int*)d_in[15];
    const int* ps = (const int*)d_in[16];
    const int* pd = (const int*)d_in[17];
    const int* es = (const int*)d_in[18];
    const int* ed = (const int*)d_in[19];
    const int* exid = (const int*)d_in[21];
    const float* kn  = (const float*)d_in[22];
    const int* hid   = (const int*)d_in[23];
    const int* hseg  = (const int*)d_in[24];
    float* out = (float*)d_out;

    cudaFuncSetAttribute(k_gemmT, cudaFuncAttributeMaxDynamicSharedMemorySize, 98304);
    cudaFuncSetAttribute(k_mlp1T, cudaFuncAttributeMaxDynamicSharedMemorySize, 65536);
    cudaFuncSetAttribute(k_mlp2T, cudaFuncAttributeMaxDynamicSharedMemorySize, 114688);

    k_zero_deg<<<(GN * NN + 255) / 256, 256>>>();
    k_degree<<<(GN * (EE / 8) + 255) / 256, 256>>>(ss, sd, ps, pd, es, ed);
    k_scan<<<GN, 1024>>>();
    k_fill<<<(GN * (EE / 8) + 255) / 256, 256>>>(ss, sd, ps, pd, es, ed);
    k_init<<<(NN * KD + 255) / 256, 256>>>(ent);
    k_wconv<<<(GN * 4 * KD * KD + KD * H1 + H1 * H2P + 4 * KD + 255) / 256, 256>>>(
        gcnW, gcnB, W1, W2);

    for (int l = 0; l < 4; l++) {
        k_agg<<<(GN * NN * 32 + 255) / 256, 256>>>(l);
        k_gemmT<<<NN / 128, 256, 98304>>>(l);
    }

    k_segstart<<<(BB + 1 + 255) / 256, 256>>>(hseg);
    k_stu<<<(BB * 32 + 255) / 256, 256>>>(hid);
    k_cvec<<<1, 256>>>(fsW, feW);
    k_x<<<(BB * 32 + 255) / 256, 256>>>(fsW, fsB, feW, feB, disc, exid, kn);

    dim3 g1(BB / 128, H1 / 128);
    k_mlp1T<<<g1, 256, 65536>>>(b1);
    k_mlp2T<<<BB / 128, 256, 114688>>>(b2);
    k_out<<<(BB * 32 + 255) / 256, 256>>>(W3, b3, out);
}

// round 6
// speedup vs baseline: 1.7138x; 1.0510x over previous
#include <cuda_runtime.h>
#include <cuda_fp16.h>
#include <cuda_fp8.h>
#include <mma.h>

using namespace nvcuda;

#define GN 3
constexpr int NN = 16512;     // K + EXER entities  (= 129 * 128 exactly)
constexpr int KD = 128;       // embedding dim
constexpr int EE = 400000;    // edges per graph (divisible by 8)
constexpr int BB = 4096;      // batch
constexpr int TT = 204800;    // history length
constexpr int H1 = 512;
constexpr int H2 = 216;
constexpr int H2P = 224;      // padded to 14*16

// ---------------- scratch (static device globals; no allocation) ----------------
__device__ int            d_deg_s[GN][NN];
__device__ int            d_deg_d[GN][NN];
__device__ int            d_rowp[GN][NN + 1];
__device__ int            d_cur[GN][NN];
__device__ unsigned short d_csru[GN][EE];  // src idx only (fits 16 bits)
__device__ __half         d_rs[GN][NN];    // rsqrt(max(deg_s,1)) fp16
__device__ unsigned char  d_h8a[NN * KD];  // fp8 e4m3 activations (gather source)
__device__ unsigned char  d_h8b[NN * KD];
__device__ __half         d_aggh[GN][NN * KD];   // fp16 aggregation (A for tensor GEMM)
__device__ __half         d_Wh[GN * 4 * KD * KD];// fp16 GCN weights [g][l][k][n]
__device__ float          d_biasC[4][KD];        // per-layer combined bias (sum over g)
__device__ __half         d_W1h[KD * H1];
__device__ __half         d_W2h[H1 * H2P];       // zero-padded cols
__device__ float          d_sumA[NN * KD];  // entity_emb + h1+h2+h3+h4  (full = /5)
__device__ float          d_sumL[NN * KD];  // h3 (partial)
__device__ __half         d_sumLh[NN * KD]; // h3 + h4 fp16 (disc_full*2) for k_stu
__device__ float          d_stu[BB * KD];
__device__ int            d_segs[BB + 1];
__device__ float          d_cvec[2 * KD];
__device__ __half         d_xh[BB * KD];
__device__ __half         d_x1h[BB * H1];
__device__ float          d_x2[BB * H2];

__device__ __forceinline__ float sigm(float x) { return 1.f / (1.f + __expf(-x)); }

// ---------------- CSR build ----------------
__global__ void k_zero_deg() {
    int i = blockIdx.x * blockDim.x + threadIdx.x;
    if (i < GN * NN) { ((int*)d_deg_s)[i] = 0; ((int*)d_deg_d)[i] = 0; }
}

// 8 edges per thread -> MLP=8 on the L2 atomics
__global__ void k_degree(const int* __restrict__ s0, const int* __restrict__ d0,
                         const int* __restrict__ s1, const int* __restrict__ d1,
                         const int* __restrict__ s2, const int* __restrict__ d2) {
    int i = blockIdx.x * blockDim.x + threadIdx.x;
    const int Q = EE / 8;
    if (i >= GN * Q) return;
    int g = i / Q, e8 = (i - g * Q) * 8;
    const int* S = (g == 0) ? s0 : (g == 1) ? s1 : s2;
    const int* D = (g == 0) ? d0 : (g == 1) ? d1 : d2;
    int4 sa = *(const int4*)&S[e8];
    int4 sb = *(const int4*)&S[e8 + 4];
    int4 da = *(const int4*)&D[e8];
    int4 db = *(const int4*)&D[e8 + 4];
    atomicAdd(&d_deg_s[g][sa.x], 1); atomicAdd(&d_deg_s[g][sa.y], 1);
    atomicAdd(&d_deg_s[g][sa.z], 1); atomicAdd(&d_deg_s[g][sa.w], 1);
    atomicAdd(&d_deg_s[g][sb.x], 1); atomicAdd(&d_deg_s[g][sb.y], 1);
    atomicAdd(&d_deg_s[g][sb.z], 1); atomicAdd(&d_deg_s[g][sb.w], 1);
    atomicAdd(&d_deg_d[g][da.x], 1); atomicAdd(&d_deg_d[g][da.y], 1);
    atomicAdd(&d_deg_d[g][da.z], 1); atomicAdd(&d_deg_d[g][da.w], 1);
    atomicAdd(&d_deg_d[g][db.x], 1); atomicAdd(&d_deg_d[g][db.y], 1);
    atomicAdd(&d_deg_d[g][db.z], 1); atomicAdd(&d_deg_d[g][db.w], 1);
}

// exclusive scan of in-degree -> row_ptr (+cursor copy). one block per graph, 1024 thr.
__global__ void k_scan() {
    __shared__ int sA[1024], sB[1024];
    int g = blockIdx.x, t = threadIdx.x;
    const int CH = (NN + 1023) / 1024;   // 17
    int base = t * CH;
    int s = 0;
    for (int i = 0; i < CH; i++) { int idx = base + i; if (idx < NN) s += d_deg_d[g][idx]; }
    sA[t] = s;
    __syncthreads();
    int* a = sA; int* b = sB;
    for (int off = 1; off < 1024; off <<= 1) {
        b[t] = a[t] + ((t >= off) ? a[t - off] : 0);
        __syncthreads();
        int* tmp = a; a = b; b = tmp;
    }
    int incl = a[t];
    int total = a[1023];
    int run = incl - s;
    for (int i = 0; i < CH; i++) {
        int idx = base + i;
        if (idx < NN) { d_rowp[g][idx] = run; d_cur[g][idx] = run; run += d_deg_d[g][idx]; }
    }
    if (t == 0) d_rowp[g][NN] = total;
}

// per-source rsqrt table (fp16)
__global__ void k_rs() {
    int i = blockIdx.x * blockDim.x + threadIdx.x;
    if (i < GN * NN)
        ((__half*)d_rs)[i] =
            __float2half_rn(rsqrtf((float)max(((const int*)d_deg_s)[i], 1)));
}

// 8 edges per thread: atomic cursor + 2-byte scatter only
__global__ void k_fill(const int* __restrict__ s0, const int* __restrict__ d0,
                       const int* __restrict__ s1, const int* __restrict__ d1,
                       const int* __restrict__ s2, const int* __restrict__ d2) {
    int i = blockIdx.x * blockDim.x + threadIdx.x;
    const int Q = EE / 8;
    if (i >= GN * Q) return;
    int g = i / Q, e8 = (i - g * Q) * 8;
    const int* S = (g == 0) ? s0 : (g == 1) ? s1 : s2;
    const int* D = (g == 0) ? d0 : (g == 1) ? d1 : d2;
    int sv[8], dv[8];
    *(int4*)&sv[0] = *(const int4*)&S[e8];
    *(int4*)&sv[4] = *(const int4*)&S[e8 + 4];
    *(int4*)&dv[0] = *(const int4*)&D[e8];
    *(int4*)&dv[4] = *(const int4*)&D[e8 + 4];
    int pos[8];
#pragma unroll
    for (int q = 0; q < 8; q++) pos[q] = atomicAdd(&d_cur[g][dv[q]], 1);
#pragma unroll
    for (int q = 0; q < 8; q++) d_csru[g][pos[q]] = (unsigned short)sv[q];
}

// init: sumA=emb, sumL=0, h0 = fp8(emb). 4 elements per thread.
__global__ void k_init(const float* __restrict__ ent) {
    int i = blockIdx.x * blockDim.x + threadIdx.x;
    if (i >= NN * KD / 4) return;
    float4 v = ((const float4*)ent)[i];
    ((float4*)d_sumA)[i] = v;
    ((float4*)d_sumL)[i] = make_float4(0.f, 0.f, 0.f, 0.f);
    __nv_fp8x2_storage_t lo =
        __nv_cvt_float2_to_fp8x2(make_float2(v.x, v.y), __NV_SATFINITE, __NV_E4M3);
    __nv_fp8x2_storage_t hi =
        __nv_cvt_float2_to_fp8x2(make_float2(v.z, v.w), __NV_SATFINITE, __NV_E4M3);
    ((unsigned*)d_h8a)[i] = (unsigned)lo | ((unsigned)hi << 16);
}

// one-shot fp16 weight conversion + bias combine + W2 padding
__global__ void k_wconv(const float* __restrict__ gcnW, const float* __restrict__ gcnB,
                        const float* __restrict__ W1, const float* __restrict__ W2) {
    int i = blockIdx.x * blockDim.x + threadIdx.x;
    const int A = GN * 4 * KD * KD;          // 196608
    const int B = A + KD * H1;               // +65536
    const int C = B + H1 * H2P;              // +114688
    const int D = C + 4 * KD;                // +512
    if (i < A) {
        d_Wh[i] = __float2half_rn(gcnW[i]);
    } else if (i < B) {
        int j = i - A;
        d_W1h[j] = __float2half_rn(W1[j]);
    } else if (i < C) {
        int j = i - B;
        int k = j / H2P, n = j - k * H2P;
        d_W2h[j] = __float2half_rn(n < H2 ? W2[k * H2 + n] : 0.f);
    } else if (i < D) {
        int j = i - C;
        int l = j >> 7, col = j & 127;
        d_biasC[l][col] = gcnB[l * KD + col] + gcnB[4 * KD + l * KD + col]
                        + gcnB[8 * KD + l * KD + col];
    }
}

// decode 16 fp8 (uint4) and HFMA2-accumulate with weight w2 into acc[8]
__device__ __forceinline__ void fma16(__half2 acc[8], uint4 v, __half2 w2) {
    const unsigned* p = &v.x;
#pragma unroll
    for (int q = 0; q < 4; q++) {
        unsigned word = p[q];
        __half2_raw hlo = __nv_cvt_fp8x2_to_halfraw2(
            (__nv_fp8x2_storage_t)(word & 0xFFFFu), __NV_E4M3);
        __half2_raw hhi = __nv_cvt_fp8x2_to_halfraw2(
            (__nv_fp8x2_storage_t)(word >> 16), __NV_E4M3);
        acc[2 * q]     = __hfma2(w2, *(__half2*)&hlo, acc[2 * q]);
        acc[2 * q + 1] = __hfma2(w2, *(__half2*)&hhi, acc[2 * q + 1]);
    }
}

// ---------------- GCN aggregation: warp per (g, dst-row), 4 edges per LDG.128 ----
// lane groups of 8 (grp = lane>>3) each take one edge; each lane covers 16 fp8 cols.
__global__ void __launch_bounds__(256) k_agg(int layer) {
    int gt = blockIdx.x * blockDim.x + threadIdx.x;
    int w = gt >> 5, lane = gt & 31;
    if (w >= GN * NN) return;
    int g = w / NN, n = w - g * NN;
    const unsigned char* __restrict__ hin = (layer & 1) ? d_h8b : d_h8a;
    int e0 = d_rowp[g][n], e1 = d_rowp[g][n + 1];
    const unsigned short* __restrict__ cs = d_csru[g];
    const __half* __restrict__ rs = d_rs[g];
    int grp = lane >> 3, sub = lane & 7;
    int colb = sub * 16;                    // byte offset within 128B row
    __half2 acc[8];
#pragma unroll
    for (int j = 0; j < 8; j++) acc[j] = __floats2half2_rn(0.f, 0.f);

    int base = e0;
    for (; base + 8 <= e1; base += 8) {     // 8 edges per iter, 2 per lane group
        int ea = base + grp, eb = base + 4 + grp;
        unsigned short sa = cs[ea], sb = cs[eb];
        __half wa = rs[sa], wb = rs[sb];
        uint4 va = *(const uint4*)(hin + (int)sa * KD + colb);
        uint4 vb = *(const uint4*)(hin + (int)sb * KD + colb);
        fma16(acc, va, __half2half2(wa));
        fma16(acc, vb, __half2half2(wb));
    }
    for (; base < e1; base += 4) {
        int e = base + grp;
        if (e < e1) {
            unsigned short sa = cs[e];
            __half wa = rs[sa];
            uint4 va = *(const uint4*)(hin + (int)sa * KD + colb);
            fma16(acc, va, __half2half2(wa));
        }
    }
    // combine the 4 lane groups (all hold same columns)
#pragma unroll
    for (int j = 0; j < 8; j++) {
        unsigned u = *(unsigned*)&acc[j];
        unsigned v = __shfl_xor_sync(0xffffffffu, u, 8);
        __half2 t = __hadd2(acc[j], *(__half2*)&v);
        unsigned u2 = *(unsigned*)&t;
        unsigned v2 = __shfl_xor_sync(0xffffffffu, u2, 16);
        acc[j] = __hadd2(t, *(__half2*)&v2);
    }
    if (grp == 0) {
        float rsd = rsqrtf((float)max(e1 - e0, 1));
        uint4 o0, o1;
        unsigned* oo = &o0.x;
#pragma unroll
        for (int j = 0; j < 8; j++) {
            float2 f = __half22float2(acc[j]);
            __half2 h = __floats2half2_rn(f.x * rsd, f.y * rsd);
            if (j == 4) oo = &o1.x;
            oo[j & 3] = *(unsigned*)&h;
        }
        __half* dst = &d_aggh[g][n * KD + colb];   // colb halves == 16*sub
        *(uint4*)dst = o0;
        *(uint4*)(dst + 8) = o1;
    }
}

// ---------------- GCN GEMM (tensor cores): h_new = sum_g aggh_g @ Wh_gl + biasC
__global__ void __launch_bounds__(256) k_gemmT(int layer) {
    extern __shared__ char smem[];
    __half* Wsm = (__half*)smem;                // 3*128*128 half = 98304 B
    float* stage = (float*)smem;                // overlay after mainloop
    int tid = threadIdx.x, w = tid >> 5, lane = tid & 31;

    {
        uint4* dst = (uint4*)Wsm;
        for (int i = tid; i < 6144; i += 256) {
            int g = i >> 11, rem = i & 2047;
            dst[i] = ((const uint4*)(d_Wh + (size_t)(g * 4 + layer) * 16384))[rem];
        }
    }
    __syncthreads();

    wmma::fragment<wmma::accumulator, 16, 16, 16, float> c[8];
#pragma unroll
    for (int n = 0; n < 8; n++) wmma::fill_fragment(c[n], 0.f);

    int row0 = blockIdx.x * 128 + w * 16;
    for (int kt = 0; kt < 24; kt++) {
        int g = kt >> 3, ks = (kt & 7) << 4;
        wmma::fragment<wmma::matrix_a, 16, 16, 16, __half, wmma::row_major> a;
        wmma::load_matrix_sync(a, d_aggh[g] + row0 * KD + ks, KD);
#pragma unroll
        for (int n = 0; n < 8; n++) {
            wmma::fragment<wmma::matrix_b, 16, 16, 16, __half, wmma::row_major> b;
            wmma::load_matrix_sync(b, Wsm + g * 16384 + ks * 128 + n * 16, 128);
            wmma::mma_sync(c[n], a, b, c[n]);
        }
    }
    __syncthreads();   // everyone done reading Wsm; reuse as stage

    float* st = stage + w * 2048;
#pragma unroll
    for (int n = 0; n < 8; n++)
        wmma::store_matrix_sync(st + n * 16, c[n], 128, wmma::mem_row_major);
    __syncwarp();

    int col0 = lane * 4;
    float4 bias = *(const float4*)&d_biasC[layer][col0];
    unsigned char* hout = (layer & 1) ? d_h8a : d_h8b;
#pragma unroll
    for (int r = 0; r < 16; r++) {
        float4 v = *(float4*)&st[r * 128 + col0];
        v.x += bias.x; v.y += bias.y; v.z += bias.z; v.w += bias.w;
        int base = (row0 + r) * KD + col0;
        __nv_fp8x2_storage_t lo =
            __nv_cvt_float2_to_fp8x2(make_float2(v.x, v.y), __NV_SATFINITE, __NV_E4M3);
        __nv_fp8x2_storage_t hi =
            __nv_cvt_float2_to_fp8x2(make_float2(v.z, v.w), __NV_SATFINITE, __NV_E4M3);
        *(unsigned*)&hout[base] = (unsigned)lo | ((unsigned)hi << 16);
        float4 sa = *(float4*)&d_sumA[base];
        sa.x += v.x; sa.y += v.y; sa.z += v.z; sa.w += v.w;
        *(float4*)&d_sumA[base] = sa;
        if (layer == 2) {
            *(float4*)&d_sumL[base] = v;       // h3
        } else if (layer == 3) {
            float4 sl = *(float4*)&d_sumL[base];
            __half2 s01 = __floats2half2_rn(sl.x + v.x, sl.y + v.y);
            __half2 s23 = __floats2half2_rn(sl.z + v.z, sl.w + v.w);
            uint2 sv2;
            sv2.x = *(unsigned*)&s01;
            sv2.y = *(unsigned*)&s23;
            *(uint2*)&d_sumLh[base] = sv2;     // h3+h4 fp16
        }
    }
}

// ---------------- head ----------------
__global__ void k_segstart(const int* __restrict__ seg) {
    int b = blockIdx.x * blockDim.x + threadIdx.x;
    if (b > BB) return;
    int lo = 0, hi = TT;
    while (lo < hi) { int m = (lo + hi) >> 1; if (seg[m] < b) lo = m + 1; else hi = m; }
    d_segs[b] = lo;
}

// stu[b] = mean over history of disc_full[K+hid] ; sumLh fp16 gather (8 B/lane)
__global__ void k_stu(const int* __restrict__ hist) {
    int gt = blockIdx.x * blockDim.x + threadIdx.x;
    int w = gt >> 5, lane = gt & 31;
    if (w >= BB) return;
    int s = d_segs[w], e = d_segs[w + 1];
    const __half* __restrict__ SL = d_sumLh;
    int col = lane * 4;
    float ax = 0.f, ay = 0.f, az = 0.f, aw = 0.f;
    int t = s;
    for (; t + 4 <= e; t += 4) {
        int4 h4 = make_int4(hist[t], hist[t + 1], hist[t + 2], hist[t + 3]);
        uint2 r0 = *(const uint2*)(SL + (KD + h4.x) * KD + col);
        uint2 r1 = *(const uint2*)(SL + (KD + h4.y) * KD + col);
        uint2 r2 = *(const uint2*)(SL + (KD + h4.z) * KD + col);
        uint2 r3 = *(const uint2*)(SL + (KD + h4.w) * KD + col);
        float2 f;
        f = __half22float2(*(__half2*)&r0.x); ax += f.x; ay += f.y;
        f = __half22float2(*(__half2*)&r0.y); az += f.x; aw += f.y;
        f = __half22float2(*(__half2*)&r1.x); ax += f.x; ay += f.y;
        f = __half22float2(*(__half2*)&r1.y); az += f.x; aw += f.y;
        f = __half22float2(*(__half2*)&r2.x); ax += f.x; ay += f.y;
        f = __half22float2(*(__half2*)&r2.y); az += f.x; aw += f.y;
        f = __half22float2(*(__half2*)&r3.x); ax += f.x; ay += f.y;
        f = __half22float2(*(__half2*)&r3.y); az += f.x; aw += f.y;
    }
    for (; t < e; t++) {
        int h = hist[t];
        uint2 r = *(const uint2*)(SL + (KD + h) * KD + col);
        float2 f;
        f = __half22float2(*(__half2*)&r.x); ax += f.x; ay += f.y;
        f = __half22float2(*(__half2*)&r.y); az += f.x; aw += f.y;
    }
    float inv = 0.5f / fmaxf((float)(e - s), 1.f);
    float4 o = make_float4(ax * inv, ay * inv, az * inv, aw * inv);
    *(float4*)&d_stu[w * KD + col] = o;
}

// c_stu[j] = (full row j) . stuW[K:],  c_exer[j] = (full row j) . exeW[K:]   (full = sumA/5)
__global__ void k_cvec(const float* __restrict__ stuW, const float* __restrict__ exeW) {
    int tid = threadIdx.x;                  // 256 threads, 1 block
    int j = tid & 127;
    bool isE = tid >= 128;
    const float* wv = isE ? (exeW + KD) : (stuW + KD);
    float s = 0.f;
    for (int k = 0; k < KD; k++) s += d_sumA[j * KD + k] * wv[k];
    d_cvec[(isE ? KD : 0) + j] = s * 0.2f;
}

__global__ void k_x(const float* __restrict__ fsW, const float* __restrict__ fsB,
                    const float* __restrict__ feW, const float* __restrict__ feB,
                    const float* __restrict__ disc, const int* __restrict__ exid,
                    const float* __restrict__ kn) {
    int gt = blockIdx.x * blockDim.x + threadIdx.x;
    int w = gt >> 5, lane = gt & 31;
    if (w >= BB) return;
    int eid = exid[w];
    float4 sv = ((const float4*)d_stu)[w * 32 + lane];
    float4 ev = ((const float4*)d_sumA)[(KD + eid) * 32 + lane];
    float4 wa = ((const float4*)fsW)[lane];
    float4 wb = ((const float4*)feW)[lane];
    float ps = sv.x * wa.x + sv.y * wa.y + sv.z * wa.z + sv.w * wa.w;
    float pe = (ev.x * wb.x + ev.y * wb.y + ev.z * wb.z + ev.w * wb.w) * 0.2f;
#pragma unroll
    for (int o = 16; o; o >>= 1) {
        ps += __shfl_xor_sync(0xffffffffu, ps, o);
        pe += __shfl_xor_sync(0xffffffffu, pe, o);
    }
    float ed = 10.f * sigm(disc[eid]);
    float4 cs = ((const float4*)d_cvec)[lane];
    float4 ce = ((const float4*)(d_cvec + KD))[lane];
    float4 kv = ((const float4*)kn)[w * 32 + lane];
    float bs = fsB[0], be = feB[0];
    float x0 = ed * (sigm(ps + cs.x + bs) - sigm(pe + ce.x + be)) * kv.x;
    float x1 = ed * (sigm(ps + cs.y + bs) - sigm(pe + ce.y + be)) * kv.y;
    float x2 = ed * (sigm(ps + cs.z + bs) - sigm(pe + ce.z + be)) * kv.z;
    float x3 = ed * (sigm(ps + cs.w + bs) - sigm(pe + ce.w + be)) * kv.w;
    __half2 h01 = __floats2half2_rn(x0, x1);
    __half2 h23 = __floats2half2_rn(x2, x3);
    uint2 hv;
    hv.x = *(unsigned*)&h01;
    hv.y = *(unsigned*)&h23;
    *(uint2*)&d_xh[w * KD + lane * 4] = hv;
}

// MLP layer 1 (tensor): x(4096x128) @ W1(128x512) -> sigmoid -> d_x1h (fp16)
__global__ void __launch_bounds__(256) k_mlp1T(const float* __restrict__ b1) {
    extern __shared__ char smem[];
    __half* Bsm = (__half*)smem;
    float* stage = (float*)smem;
    int tid = threadIdx.x, w = tid >> 5, lane = tid & 31;
    int n0 = blockIdx.y * 128;

    for (int i = tid; i < 2048; i += 256) {
        int k = i >> 4, nq = (i & 15) << 3;
        *(uint4*)&Bsm[k * 128 + nq] = *(const uint4*)&d_W1h[k * H1 + n0 + nq];
    }
    __syncthreads();

    wmma::fragment<wmma::accumulator, 16, 16, 16, float> c[8];
#pragma unroll
    for (int n = 0; n < 8; n++) wmma::fill_fragment(c[n], 0.f);

    int row0 = blockIdx.x * 128 + w * 16;
    for (int kt = 0; kt < 8; kt++) {
        wmma::fragment<wmma::matrix_a, 16, 16, 16, __half, wmma::row_major> a;
        wmma::load_matrix_sync(a, d_xh + row0 * KD + kt * 16, KD);
#pragma unroll
        for (int n = 0; n < 8; n++) {
            wmma::fragment<wmma::matrix_b, 16, 16, 16, __half, wmma::row_major> b;
            wmma::load_matrix_sync(b, Bsm + kt * 16 * 128 + n * 16, 128);
            wmma::mma_sync(c[n], a, b, c[n]);
        }
    }
    __syncthreads();

    float* st = stage + w * 2048;
#pragma unroll
    for (int n = 0; n < 8; n++)
        wmma::store_matrix_sync(st + n * 16, c[n], 128, wmma::mem_row_major);
    __syncwarp();

    int col0 = lane * 4;
    float4 bias = *(const float4*)&b1[n0 + col0];
#pragma unroll
    for (int r = 0; r < 16; r++) {
        float4 v = *(float4*)&st[r * 128 + col0];
        float y0 = sigm(v.x + bias.x);
        float y1 = sigm(v.y + bias.y);
        float y2 = sigm(v.z + bias.z);
        float y3 = sigm(v.w + bias.w);
        __half2 h01 = __floats2half2_rn(y0, y1);
        __half2 h23 = __floats2half2_rn(y2, y3);
        uint2 hv;
        hv.x = *(unsigned*)&h01;
        hv.y = *(unsigned*)&h23;
        *(uint2*)&d_x1h[(row0 + r) * H1 + n0 + col0] = hv;
    }
}

// MLP layer 2 (tensor): x1(4096x512) @ W2pad(512x224) -> sigmoid -> d_x2 (fp32, 216 cols)
__global__ void __launch_bounds__(256) k_mlp2T(const float* __restrict__ b2) {
    extern __shared__ float stage[];    // 8 * 16 * 224 floats = 114688 B
    int tid = threadIdx.x, w = tid >> 5, lane = tid & 31;

    wmma::fragment<wmma::accumulator, 16, 16, 16, float> c[14];
#pragma unroll
    for (int n = 0; n < 14; n++) wmma::fill_fragment(c[n], 0.f);

    int row0 = blockIdx.x * 128 + w * 16;
    for (int kt = 0; kt < 32; kt++) {
        wmma::fragment<wmma::matrix_a, 16, 16, 16, __half, wmma::row_major> a;
        wmma::load_matrix_sync(a, d_x1h + row0 * H1 + kt * 16, H1);
#pragma unroll
        for (int n = 0; n < 14; n++) {
            wmma::fragment<wmma::matrix_b, 16, 16, 16, __half, wmma::row_major> b;
            wmma::load_matrix_sync(b, d_W2h + kt * 16 * H2P + n * 16, H2P);
            wmma::mma_sync(c[n], a, b, c[n]);
        }
    }
    float* st = stage + w * (16 * H2P);
#pragma unroll
    for (int n = 0; n < 14; n++)
        wmma::store_matrix_sync(st + n * 16, c[n], H2P, wmma::mem_row_major);
    __syncwarp();

#pragma unroll
    for (int j = 0; j < 7; j++) {
        int col = lane * 7 + j;
        if (col < H2) {
            float bb = b2[col];
#pragma unroll
            for (int r = 0; r < 16; r++) {
                float v = st[r * H2P + col];
                d_x2[(row0 + r) * H2 + col] = sigm(v + bb);
            }
        }
    }
}

__global__ void k_out(const float* __restrict__ W3, const float* __restrict__ b3,
                      float* __restrict__ out) {
    int gt = blockIdx.x * blockDim.x + threadIdx.x;
    int w = gt >> 5, lane = gt & 31;
    if (w >= BB) return;
    float s = 0.f;
    for (int k = lane; k < H2; k += 32) s += d_x2[w * H2 + k] * W3[k];
#pragma unroll
    for (int o = 16; o; o >>= 1) s += __shfl_xor_sync(0xffffffffu, s, o);
    if (lane == 0) out[w] = sigm(s + b3[0]);
}

// ---------------- launch ----------------
extern "C" void kernel_launch(void* const* d_in, const int* in_sizes, int n_in,
                              void* d_out, int out_size) {
    const float* ent  = (const float*)d_in[0];
    const float* gcnW = (const float*)d_in[1];
    const float* gcnB = (const float*)d_in[2];
    const float* fsW  = (const float*)d_in[3];
    const float* fsB  = (const float*)d_in[4];
    const float* feW  = (const float*)d_in[5];
    const float* feB  = (const float*)d_in[6];
    const float* disc = (const float*)d_in[7];
    const float* W1   = (const float*)d_in[8];
    const float* b1   = (const float*)d_in[9];
    const float* W2   = (const float*)d_in[10];
    const float* b2   = (const float*)d_in[11];
    const float* W3   = (const float*)d_in[12];
    const float* b3   = (const float*)d_in[13];
    const int* ss = (const int*)d_in[14];
    const int* sd = (const int*)d_in[15];
    const int* ps = (const int*)d_in[16];
    const int* pd = (const int*)d_in[17];
    const int* es = (const int*)d_in[18];
    const int* ed = (const int*)d_in[19];
    const int* exid = (const int*)d_in[21];
    const float* kn  = (const float*)d_in[22];
    const int* hid   = (const int*)d_in[23];
    const int* hseg  = (const int*)d_in[24];
    float* out = (float*)d_out;

    cudaFuncSetAttribute(k_gemmT, cudaFuncAttributeMaxDynamicSharedMemorySize, 98304);
    cudaFuncSetAttribute(k_mlp1T, cudaFuncAttributeMaxDynamicSharedMemorySize, 65536);
    cudaFuncSetAttribute(k_mlp2T, cudaFuncAttributeMaxDynamicSharedMemorySize, 114688);

    k_zero_deg<<<(GN * NN + 255) / 256, 256>>>();
    k_degree<<<(GN * (EE / 8) + 255) / 256, 256>>>(ss, sd, ps, pd, es, ed);
    k_scan<<<GN, 1024>>>();
    k_rs<<<(GN * NN + 255) / 256, 256>>>();
    k_fill<<<(GN * (EE / 8) + 255) / 256, 256>>>(ss, sd, ps, pd, es, ed);
    k_init<<<(NN * KD / 4 + 255) / 256, 256>>>(ent);
    k_wconv<<<(GN * 4 * KD * KD + KD * H1 + H1 * H2P + 4 * KD + 255) / 256, 256>>>(
        gcnW, gcnB, W1, W2);

    for (int l = 0; l < 4; l++) {
        k_agg<<<(GN * NN * 32 + 255) / 256, 256>>>(l);
        k_gemmT<<<NN / 128, 256, 98304>>>(l);
    }

    k_segstart<<<(BB + 1 + 255) / 256, 256>>>(hseg);
    k_stu<<<(BB * 32 + 255) / 256, 256>>>(hid);
    k_cvec<<<1, 256>>>(fsW, feW);
    k_x<<<(BB * 32 + 255) / 256, 256>>>(fsW, fsB, feW, feB, disc, exid, kn);

    dim3 g1(BB / 128, H1 / 128);
    k_mlp1T<<<g1, 256, 65536>>>(b1);
    k_mlp2T<<<BB / 128, 256, 114688>>>(b2);
    k_out<<<(BB * 32 + 255) / 256, 256>>>(W3, b3, out);
}